// round 3
// baseline (speedup 1.0000x reference)
#include <cuda_runtime.h>
#include <cstdint>
#include <cstddef>

// Problem constants
#define PDIM 36
#define BB 4
#define NR 10
#define BN 40
#define RELD 7
#define RELC 256
#define LSTM 512
#define IMGF 2048
#define ROWS (BN*PDIM)          // 1440
#define RELROWS (BB*PDIM*PDIM)  // 5184
#define F2 (2*IMGF)             // 4096

// ---------------------------------------------------------------------------
// Scratch (device globals; no allocations allowed)
// ---------------------------------------------------------------------------
__device__ float g_relS [RELROWS*RELC];   // sigmoid(relation@Wcr+bcr)           5.3MB
__device__ float g_relC [RELROWS*RELC];   // relS @ Wc[:256,:]                   5.3MB
__device__ float g_v    [BN*RELC];        // ques1 * Wrw
__device__ float g_u    [BN*RELC];        // ques1 * Wg
__device__ float g_imgC [ROWS*RELC];      // img @ Wc[256:,:] + bc               1.5MB
__device__ float g_D2   [ROWS];           // imgC . u
__device__ float g_gw   [ROWS*PDIM];      // attention weights gw
__device__ float g_cii  [ROWS*F2];        // [img, img_ws]                      23.6MB
__device__ float g_gatec[ROWS*F2];        // sigmoid(cii@Ww+bw)*cii             23.6MB

__device__ __forceinline__ float sigmoidf_(float x) {
    return 1.0f / (1.0f + __expf(-x));
}

// ---------------------------------------------------------------------------
// K1: relS = sigmoid(relation @ Wcr + bcr)   (5184 rows x 256)
// ---------------------------------------------------------------------------
__global__ void rels_kernel(const float* __restrict__ relation,
                            const float* __restrict__ Wcr,
                            const float* __restrict__ bcr)
{
    int r = blockIdx.x;        // 0..5183
    int c = threadIdx.x;       // 0..255
    __shared__ float rd[RELD];
    if (c < RELD) rd[c] = relation[r*RELD + c];
    __syncthreads();
    float acc = bcr[c];
#pragma unroll
    for (int d = 0; d < RELD; ++d) acc += rd[d] * Wcr[d*RELC + c];
    g_relS[(size_t)r*RELC + c] = sigmoidf_(acc);
}

// ---------------------------------------------------------------------------
// K2: per-round question vectors: v = sig(ques@Wq+bq)*Wrw ; u = same * Wg
// ---------------------------------------------------------------------------
__global__ void ques_kernel(const float* __restrict__ ques,
                            const float* __restrict__ Wq,
                            const float* __restrict__ bq,
                            const float* __restrict__ Wrw,
                            const float* __restrict__ Wg)
{
    int bn = blockIdx.x;       // 0..39
    int c  = threadIdx.x;      // 0..255
    __shared__ float q[LSTM];
    q[c]       = ques[bn*LSTM + c];
    q[c + 256] = ques[bn*LSTM + c + 256];
    __syncthreads();
    float acc = bq[c];
    for (int k = 0; k < LSTM; ++k) acc += q[k] * Wq[k*RELC + c];
    float s = sigmoidf_(acc);
    g_v[bn*RELC + c] = s * Wrw[c];
    g_u[bn*RELC + c] = s * Wg[c];
}

// ---------------------------------------------------------------------------
// Generic double-buffered SGEMM: C[M,N] = A[M,K] @ B[K,N] (+ epilogue)
// Requires: K % 16 == 0, N % 128 == 0. M is bounds-checked.
// EPI: 0 = plain, 1 = +bias, 2 = sigmoid(acc+bias)*aux  (gate)
// ---------------------------------------------------------------------------
template<int EPI>
__global__ __launch_bounds__(256, 2)
void sgemm_k(int M, int N, int K,
             const float* __restrict__ A,
             const float* __restrict__ B,
             const float* __restrict__ bias,
             const float* __restrict__ aux,
             float* __restrict__ C)
{
    __shared__ float As[2][16][128];   // transposed A tile
    __shared__ float Bs[2][16][128];

    const int m0 = blockIdx.y * 128;
    const int n0 = blockIdx.x * 128;
    const int tid = threadIdx.x;
    const int tx = tid & 15;           // N direction
    const int ty = tid >> 4;           // M direction

    // load mapping
    const int arow  = tid >> 1;             // 0..127
    const int akoff = (tid & 1) * 8;        // 0 or 8
    const int brow  = tid >> 4;             // 0..15
    const int bcol  = (tid & 15) * 8;       // 0..120

    float acc[8][8];
#pragma unroll
    for (int i = 0; i < 8; ++i)
#pragma unroll
        for (int j = 0; j < 8; ++j) acc[i][j] = 0.0f;

    const int ntiles = K >> 4;

    // ---- prologue: tile 0 -> buf 0
    {
        int gr = m0 + arow;
        float4 a0 = make_float4(0.f,0.f,0.f,0.f), a1 = a0;
        if (gr < M) {
            const float* ap = A + (size_t)gr*K + akoff;
            a0 = *reinterpret_cast<const float4*>(ap);
            a1 = *reinterpret_cast<const float4*>(ap + 4);
        }
        As[0][akoff+0][arow] = a0.x; As[0][akoff+1][arow] = a0.y;
        As[0][akoff+2][arow] = a0.z; As[0][akoff+3][arow] = a0.w;
        As[0][akoff+4][arow] = a1.x; As[0][akoff+5][arow] = a1.y;
        As[0][akoff+6][arow] = a1.z; As[0][akoff+7][arow] = a1.w;
        const float* bp = B + (size_t)brow*N + n0 + bcol;
        *reinterpret_cast<float4*>(&Bs[0][brow][bcol])     = *reinterpret_cast<const float4*>(bp);
        *reinterpret_cast<float4*>(&Bs[0][brow][bcol + 4]) = *reinterpret_cast<const float4*>(bp + 4);
    }
    __syncthreads();

    for (int t = 0; t < ntiles; ++t) {
        const int buf = t & 1;
        float4 pa0, pa1, pb0, pb1;
        const bool pf = (t + 1) < ntiles;
        if (pf) {
            const int k0n = (t + 1) << 4;
            int gr = m0 + arow;
            pa0 = make_float4(0.f,0.f,0.f,0.f); pa1 = pa0;
            if (gr < M) {
                const float* ap = A + (size_t)gr*K + k0n + akoff;
                pa0 = *reinterpret_cast<const float4*>(ap);
                pa1 = *reinterpret_cast<const float4*>(ap + 4);
            }
            const float* bp = B + (size_t)(k0n + brow)*N + n0 + bcol;
            pb0 = *reinterpret_cast<const float4*>(bp);
            pb1 = *reinterpret_cast<const float4*>(bp + 4);
        }

#pragma unroll
        for (int kk = 0; kk < 16; ++kk) {
            float4 av0 = *reinterpret_cast<const float4*>(&As[buf][kk][ty*8]);
            float4 av1 = *reinterpret_cast<const float4*>(&As[buf][kk][ty*8 + 4]);
            float4 bv0 = *reinterpret_cast<const float4*>(&Bs[buf][kk][tx*8]);
            float4 bv1 = *reinterpret_cast<const float4*>(&Bs[buf][kk][tx*8 + 4]);
            float ar[8] = {av0.x,av0.y,av0.z,av0.w,av1.x,av1.y,av1.z,av1.w};
            float br[8] = {bv0.x,bv0.y,bv0.z,bv0.w,bv1.x,bv1.y,bv1.z,bv1.w};
#pragma unroll
            for (int i = 0; i < 8; ++i)
#pragma unroll
                for (int j = 0; j < 8; ++j)
                    acc[i][j] += ar[i] * br[j];
        }

        if (pf) {
            const int nb = buf ^ 1;
            As[nb][akoff+0][arow] = pa0.x; As[nb][akoff+1][arow] = pa0.y;
            As[nb][akoff+2][arow] = pa0.z; As[nb][akoff+3][arow] = pa0.w;
            As[nb][akoff+4][arow] = pa1.x; As[nb][akoff+5][arow] = pa1.y;
            As[nb][akoff+6][arow] = pa1.z; As[nb][akoff+7][arow] = pa1.w;
            *reinterpret_cast<float4*>(&Bs[nb][brow][bcol])     = pb0;
            *reinterpret_cast<float4*>(&Bs[nb][brow][bcol + 4]) = pb1;
        }
        __syncthreads();
    }

    // ---- epilogue
    const int cn0 = n0 + tx*8;
#pragma unroll
    for (int i = 0; i < 8; ++i) {
        int gm = m0 + ty*8 + i;
        if (gm < M) {
            float* crow = C + (size_t)gm*N + cn0;
#pragma unroll
            for (int jj = 0; jj < 8; jj += 4) {
                float vals[4];
#pragma unroll
                for (int e = 0; e < 4; ++e) {
                    float v = acc[i][jj+e];
                    if (EPI >= 1) v += bias[cn0 + jj + e];
                    if (EPI == 2) {
                        float gte = sigmoidf_(v);
                        v = gte * aux[(size_t)gm*N + cn0 + jj + e];
                    }
                    vals[e] = v;
                }
                float4 r; r.x = vals[0]; r.y = vals[1]; r.z = vals[2]; r.w = vals[3];
                *reinterpret_cast<float4*>(crow + jj) = r;
            }
        }
    }
}

// ---------------------------------------------------------------------------
// K4: D2[bn,j] = imgC[bn,j,:] . u[bn,:]
// ---------------------------------------------------------------------------
__global__ void d2_kernel()
{
    int row = blockIdx.x;      // 0..1439 = bn*36 + j
    int bn  = row / PDIM;
    int tid = threadIdx.x;     // 256
    float p = g_imgC[(size_t)row*RELC + tid] * g_u[bn*RELC + tid];
    __shared__ float sr[8];
#pragma unroll
    for (int off = 16; off; off >>= 1) p += __shfl_xor_sync(0xffffffffu, p, off);
    if ((tid & 31) == 0) sr[tid >> 5] = p;
    __syncthreads();
    if (tid == 0) {
        float s = 0.f;
#pragma unroll
        for (int k = 0; k < 8; ++k) s += sr[k];
        g_D2[row] = s;
    }
}

// ---------------------------------------------------------------------------
// K5: per (bn,i): rw softmax -> gw softmax (cat never materialized)
// tiled mapping: R = m*1296 + i*36 + j, si = R/360, sj = j
// ---------------------------------------------------------------------------
__global__ void gw_kernel()
{
    int blk = blockIdx.x;                 // 0..1439
    int bn = blk / PDIM, i = blk % PDIM;
    int b = bn / NR, m = bn % NR;
    int tid = threadIdx.x;                // 128
    int w = tid >> 5, lane = tid & 31;

    __shared__ float sL[PDIM], sD[PDIM], sred[2];

    const float* vv = g_v + bn*RELC;
    const float* uu = g_u + bn*RELC;

    for (int j = w; j < PDIM; j += 4) {
        int R  = m*(PDIM*PDIM) + i*PDIM + j;
        int si = R / (NR*PDIM);
        size_t rowbase = ((size_t)b*PDIM*PDIM + (size_t)si*PDIM + j) * RELC;
        const float* rs = g_relS + rowbase;
        const float* rc = g_relC + rowbase;
        float s1 = 0.f, s2 = 0.f;
        for (int c = lane; c < RELC; c += 32) {
            s1 += rs[c] * vv[c];
            s2 += rc[c] * uu[c];
        }
#pragma unroll
        for (int off = 16; off; off >>= 1) {
            s1 += __shfl_xor_sync(0xffffffffu, s1, off);
            s2 += __shfl_xor_sync(0xffffffffu, s2, off);
        }
        if (lane == 0) { sL[j] = s1; sD[j] = s2; }
    }
    __syncthreads();

    // softmax(rw logits) over j
    if (tid == 0) { float mx = -1e30f; for (int j=0;j<PDIM;++j) mx = fmaxf(mx, sL[j]); sred[0] = mx; }
    __syncthreads();
    if (tid < PDIM) sL[tid] = __expf(sL[tid] - sred[0]);
    __syncthreads();
    if (tid == 0) { float s = 0.f; for (int j=0;j<PDIM;++j) s += sL[j]; sred[1] = 1.0f / s; }
    __syncthreads();
    // gw logits = rw * D1 + D2
    if (tid < PDIM) sL[tid] = sL[tid] * sred[1] * sD[tid] + g_D2[bn*PDIM + tid];
    __syncthreads();
    if (tid == 0) { float mx = -1e30f; for (int j=0;j<PDIM;++j) mx = fmaxf(mx, sL[j]); sred[0] = mx; }
    __syncthreads();
    if (tid < PDIM) sL[tid] = __expf(sL[tid] - sred[0]);
    __syncthreads();
    if (tid == 0) { float s = 0.f; for (int j=0;j<PDIM;++j) s += sL[j]; sred[1] = 1.0f / s; }
    __syncthreads();
    if (tid < PDIM) g_gw[(size_t)blk*PDIM + tid] = sL[tid] * sred[1];
}

// ---------------------------------------------------------------------------
// K6: img_ws[bn,i,f] = sum_j gw[bn,i,j]*img[bn,j,f]; build cii = [img, img_ws]
// grid: (8 fchunks, 40 bn), 256 threads
// ---------------------------------------------------------------------------
__global__ void imgws_kernel(const float* __restrict__ img)
{
    int chunk = blockIdx.x, bn = blockIdx.y;
    int tid = threadIdx.x;
    __shared__ float sg[PDIM*PDIM];
    for (int t = tid; t < PDIM*PDIM; t += 256) sg[t] = g_gw[(size_t)bn*PDIM*PDIM + t];
    __syncthreads();

    int f = chunk*256 + tid;
    float acc[PDIM];
#pragma unroll
    for (int i = 0; i < PDIM; ++i) acc[i] = 0.f;

    const float* ib = img + (size_t)bn*PDIM*IMGF + f;
#pragma unroll 4
    for (int j = 0; j < PDIM; ++j) {
        float vj = ib[(size_t)j*IMGF];
#pragma unroll
        for (int i = 0; i < PDIM; ++i) acc[i] += sg[i*PDIM + j] * vj;
    }
    float* cb = g_cii + (size_t)bn*PDIM*F2 + f;
#pragma unroll
    for (int i = 0; i < PDIM; ++i) {
        cb[(size_t)i*F2 + IMGF] = acc[i];
        cb[(size_t)i*F2]        = ib[(size_t)i*IMGF];
    }
}

// ---------------------------------------------------------------------------
// Launch
// ---------------------------------------------------------------------------
extern "C" void kernel_launch(void* const* d_in, const int* in_sizes, int n_in,
                              void* d_out, int out_size)
{
    const float* relation = (const float*)d_in[0];
    const float* img      = (const float*)d_in[1];
    const float* ques     = (const float*)d_in[2];
    const float* Wcr      = (const float*)d_in[3];
    const float* bcr      = (const float*)d_in[4];
    const float* Wq       = (const float*)d_in[5];
    const float* bq       = (const float*)d_in[6];
    const float* Wrw      = (const float*)d_in[7];
    // d_in[8] = brw (cancels in softmax)
    const float* Wc       = (const float*)d_in[9];
    const float* bc       = (const float*)d_in[10];
    const float* Wg       = (const float*)d_in[11];
    // d_in[12] = bg (cancels in softmax)
    const float* Ww       = (const float*)d_in[13];
    const float* bw       = (const float*)d_in[14];
    const float* Wi       = (const float*)d_in[15];
    const float* bi       = (const float*)d_in[16];
    float* out = (float*)d_out;

    float *p_relS, *p_relC, *p_imgC, *p_cii, *p_gatec;
    cudaGetSymbolAddress((void**)&p_relS,  g_relS);
    cudaGetSymbolAddress((void**)&p_relC,  g_relC);
    cudaGetSymbolAddress((void**)&p_imgC,  g_imgC);
    cudaGetSymbolAddress((void**)&p_cii,   g_cii);
    cudaGetSymbolAddress((void**)&p_gatec, g_gatec);

    // 1. relS = sigmoid(relation @ Wcr + bcr)
    rels_kernel<<<RELROWS, RELC>>>(relation, Wcr, bcr);
    // 2. question vectors
    ques_kernel<<<BN, RELC>>>(ques, Wq, bq, Wrw, Wg);
    // 3. relC = relS @ Wc[:256,:]            (M=5184, N=256, K=256)
    sgemm_k<0><<<dim3(RELC/128, (RELROWS+127)/128), 256>>>(
        RELROWS, RELC, RELC, p_relS, Wc, nullptr, nullptr, p_relC);
    // 4. imgC = img @ Wc[256:,:] + bc        (M=1440, N=256, K=2048)
    sgemm_k<1><<<dim3(RELC/128, (ROWS+127)/128), 256>>>(
        ROWS, RELC, IMGF, img, Wc + RELC*RELC, bc, nullptr, p_imgC);
    // 5. D2 = imgC . u
    d2_kernel<<<ROWS, RELC>>>();
    // 6. attention weights gw (rw softmax -> gw softmax), cat never built
    gw_kernel<<<ROWS, 128>>>();
    // 7. img_ws + assemble cii
    imgws_kernel<<<dim3(IMGF/256, BN), 256>>>(img);
    // 8. gated = sigmoid(cii@Ww + bw) * cii  (M=1440, N=4096, K=4096)
    sgemm_k<2><<<dim3(F2/128, (ROWS+127)/128), 256>>>(
        ROWS, F2, F2, p_cii, Ww, bw, p_cii, p_gatec);
    // 9. out = gated @ Wi + bi               (M=1440, N=2048, K=4096)
    sgemm_k<1><<<dim3(IMGF/128, (ROWS+127)/128), 256>>>(
        ROWS, IMGF, F2, p_gatec, Wi, bi, nullptr, out);
}

// round 5
// speedup vs baseline: 2.3347x; 2.3347x over previous
#include <cuda_runtime.h>
#include <cuda_bf16.h>
#include <cstdint>
#include <cstddef>

// Problem constants
#define PDIM 36
#define BB 4
#define NR 10
#define BN 40
#define RELD 7
#define RELC 256
#define LSTM 512
#define IMGF 2048
#define ROWS (BN*PDIM)          // 1440
#define RELROWS (BB*PDIM*PDIM)  // 5184
#define F2 (2*IMGF)             // 4096

// ===========================================================================
// Helpers
// ===========================================================================
__device__ __forceinline__ uint32_t smem_u32(const void* p) {
    uint32_t a;
    asm("{ .reg .u64 t; cvta.to.shared.u64 t, %1; cvt.u32.u64 %0, t; }" : "=r"(a) : "l"(p));
    return a;
}
__device__ __forceinline__ float sigmoidf_(float x) { return 1.0f / (1.0f + __expf(-x)); }
__device__ __forceinline__ void split2(float x, __nv_bfloat16& h, __nv_bfloat16& l) {
    h = __float2bfloat16(x);
    l = __float2bfloat16(x - __bfloat162float(h));
}
#define SWZ128(off) ((off) ^ (((off) >> 3) & 0x70))

__device__ __forceinline__ void cp_async16(uint32_t dst, const void* src, int szbytes) {
    asm volatile("cp.async.cg.shared.global [%0], [%1], 16, %2;"
                 :: "r"(dst), "l"(src), "r"(szbytes) : "memory");
}
#define CP_COMMIT() asm volatile("cp.async.commit_group;" ::: "memory")
#define CP_WAIT1()  asm volatile("cp.async.wait_group 1;" ::: "memory")
#define CP_WAIT0()  asm volatile("cp.async.wait_group 0;" ::: "memory")

__device__ __forceinline__ void ldm4(uint32_t* r, uint32_t a) {
    asm volatile("ldmatrix.sync.aligned.m8n8.x4.shared.b16 {%0,%1,%2,%3}, [%4];"
                 : "=r"(r[0]), "=r"(r[1]), "=r"(r[2]), "=r"(r[3]) : "r"(a));
}
__device__ __forceinline__ void mma16816(float* c, const uint32_t* a, uint32_t b0, uint32_t b1) {
    asm volatile("mma.sync.aligned.m16n8k16.row.col.f32.bf16.bf16.f32 "
                 "{%0,%1,%2,%3}, {%4,%5,%6,%7}, {%8,%9}, {%0,%1,%2,%3};"
                 : "+f"(c[0]), "+f"(c[1]), "+f"(c[2]), "+f"(c[3])
                 : "r"(a[0]), "r"(a[1]), "r"(a[2]), "r"(a[3]), "r"(b0), "r"(b1));
}

// ===========================================================================
// Scratch (device globals; no allocations allowed)
// ===========================================================================
__device__ float g_relS [RELROWS*RELC];
__device__ float g_relC [RELROWS*RELC];
__device__ float g_v    [BN*RELC];
__device__ float g_u    [BN*RELC];
__device__ float g_imgC [ROWS*RELC];
__device__ float g_D2   [ROWS];
__device__ float g_gw   [ROWS*PDIM];
__device__ float g_cii  [ROWS*F2];
// bf16 hi/lo operand splits
__device__ __nv_bfloat16 g_rSh[RELROWS*RELC], g_rSl[RELROWS*RELC];
__device__ __nv_bfloat16 g_iAh[ROWS*IMGF],    g_iAl[ROWS*IMGF];
__device__ __nv_bfloat16 g_cAh[(size_t)ROWS*F2], g_cAl[(size_t)ROWS*F2];
__device__ __nv_bfloat16 g_gAh[(size_t)ROWS*F2], g_gAl[(size_t)ROWS*F2];
__device__ __nv_bfloat16 g_B1h[RELC*RELC],    g_B1l[RELC*RELC];
__device__ __nv_bfloat16 g_B2h[RELC*IMGF],    g_B2l[RELC*IMGF];
__device__ __nv_bfloat16 g_Bwh[(size_t)F2*F2],   g_Bwl[(size_t)F2*F2];
__device__ __nv_bfloat16 g_Bih[(size_t)IMGF*F2], g_Bil[(size_t)IMGF*F2];

// ===========================================================================
// K1: relS = sigmoid(relation @ Wcr + bcr) + bf16 split
// ===========================================================================
__global__ void rels_kernel(const float* __restrict__ relation,
                            const float* __restrict__ Wcr,
                            const float* __restrict__ bcr)
{
    int r = blockIdx.x, c = threadIdx.x;
    __shared__ float rd[RELD];
    if (c < RELD) rd[c] = relation[r*RELD + c];
    __syncthreads();
    float acc = bcr[c];
#pragma unroll
    for (int d = 0; d < RELD; ++d) acc += rd[d] * Wcr[d*RELC + c];
    float s = sigmoidf_(acc);
    size_t idx = (size_t)r*RELC + c;
    g_relS[idx] = s;
    __nv_bfloat16 h, l; split2(s, h, l);
    g_rSh[idx] = h; g_rSl[idx] = l;
}

// ===========================================================================
// K2: question vectors
// ===========================================================================
__global__ void ques_kernel(const float* __restrict__ ques,
                            const float* __restrict__ Wq,
                            const float* __restrict__ bq,
                            const float* __restrict__ Wrw,
                            const float* __restrict__ Wg)
{
    int bn = blockIdx.x, c = threadIdx.x;
    __shared__ float q[LSTM];
    q[c] = ques[bn*LSTM + c];
    q[c + 256] = ques[bn*LSTM + c + 256];
    __syncthreads();
    float acc = bq[c];
    for (int k = 0; k < LSTM; ++k) acc += q[k] * Wq[k*RELC + c];
    float s = sigmoidf_(acc);
    g_v[bn*RELC + c] = s * Wrw[c];
    g_u[bn*RELC + c] = s * Wg[c];
}

// ===========================================================================
// Elementwise bf16 hi/lo split
// ===========================================================================
__global__ void split_kernel(const float* __restrict__ src, size_t n,
                             __nv_bfloat16* __restrict__ oh, __nv_bfloat16* __restrict__ ol)
{
    size_t i = (size_t)blockIdx.x * blockDim.x + threadIdx.x;
    size_t stride = (size_t)gridDim.x * blockDim.x;
    for (; i < n; i += stride) {
        __nv_bfloat16 h, l; split2(src[i], h, l);
        oh[i] = h; ol[i] = l;
    }
}

// ===========================================================================
// Weight transpose + split: W[K,N] fp32 -> Bh/Bl [N,K] bf16
// ===========================================================================
__global__ void tsplit_kernel(const float* __restrict__ W, int K, int N,
                              __nv_bfloat16* __restrict__ Bh, __nv_bfloat16* __restrict__ Bl)
{
    __shared__ float tile[32][33];
    int n0 = blockIdx.x * 32, k0 = blockIdx.y * 32;
    int tx = threadIdx.x, ty = threadIdx.y;
#pragma unroll
    for (int r = 0; r < 4; ++r)
        tile[ty + r*8][tx] = W[(size_t)(k0 + ty + r*8) * N + n0 + tx];
    __syncthreads();
#pragma unroll
    for (int r = 0; r < 4; ++r) {
        int n = n0 + ty + r*8, k = k0 + tx;
        float v = tile[tx][ty + r*8];
        __nv_bfloat16 h, l; split2(v, h, l);
        Bh[(size_t)n*K + k] = h;
        Bl[(size_t)n*K + k] = l;
    }
}

// ===========================================================================
// bf16-split GEMM via mma.sync (HMMA): C[M,N] = (Ah+Al)@(Bh+Bl)^T
// CTA tile 128x128, BK=64 bf16 (128B SW128 rows), 8 warps 2x4 (warp 64x32),
// cp.async 2-stage pipeline. 3 terms: AhBh + AhBl + AlBh.
// EPI: 0 plain fp32, 1 +bias fp32, 2 sigmoid(acc+bias)*aux -> bf16 hi/lo
// ===========================================================================
#define STAGE_B 65536          // 4 tiles x 16KB
#define HG_SMEM (2*STAGE_B)

template<int EPI>
__global__ __launch_bounds__(256, 1)
void hgemm(int M, int N, int K,
           const __nv_bfloat16* __restrict__ Ah, const __nv_bfloat16* __restrict__ Al,
           const __nv_bfloat16* __restrict__ Bh, const __nv_bfloat16* __restrict__ Bl,
           const float* __restrict__ bias, const float* __restrict__ aux,
           float* __restrict__ C,
           __nv_bfloat16* __restrict__ Ch, __nv_bfloat16* __restrict__ Cl)
{
    extern __shared__ char sm[];
    const uint32_t sbase = smem_u32(sm);

    const int tid = threadIdx.x;
    const int lid = tid & 31;
    const int wid = tid >> 5;
    const int wm = wid & 1;        // 0..1  (M dir, 64 each)
    const int wn = wid >> 1;       // 0..3  (N dir, 32 each)
    const int m0 = blockIdx.y * 128;
    const int n0 = blockIdx.x * 128;

    float acc[4][4][4];
#pragma unroll
    for (int i = 0; i < 4; ++i)
#pragma unroll
        for (int j = 0; j < 4; ++j)
#pragma unroll
            for (int e = 0; e < 4; ++e) acc[i][j][e] = 0.f;

    // ---- loader mapping: 2 threads per row, 4 x 16B segments each
    const int lrow = tid >> 1;                 // 0..127
    const int lseg = (tid & 1) * 4;            // 0 or 4
    const int gmrow = m0 + lrow;
    const int a_ok = (gmrow < M) ? 16 : 0;
    const size_t aoff = (size_t)(a_ok ? gmrow : 0) * K;
    const size_t boff = (size_t)(n0 + lrow) * K;

    const int nch = K >> 6;   // K/64

    auto load_stage = [&](int c, int buf) {
        const int k0 = c << 6;
        const uint32_t sb = sbase + buf * STAGE_B;
        const char* pAh = (const char*)(Ah + aoff + k0);
        const char* pAl = (const char*)(Al + aoff + k0);
        const char* pBh = (const char*)(Bh + boff + k0);
        const char* pBl = (const char*)(Bl + boff + k0);
#pragma unroll
        for (int s = 0; s < 4; ++s) {
            const int colb = (lseg + s) * 16;
            const uint32_t sw = SWZ128((uint32_t)(lrow * 128 + colb));
            cp_async16(sb + sw,             pAh + colb, a_ok);
            cp_async16(sb + 16384 + sw,     pAl + colb, a_ok);
            cp_async16(sb + 32768 + sw,     pBh + colb, 16);
            cp_async16(sb + 49152 + sw,     pBl + colb, 16);
        }
        CP_COMMIT();
    };

    // ---- fragment lane components
    const int matA  = lid >> 3;
    const int rowA  = (lid & 7) + ((matA & 1) << 3);
    const int kselA = (matA >> 1) << 4;             // 0 or 16 bytes
    const int rowB  = (lid & 7) + ((matA >> 1) << 3);
    const int kselB = (matA & 1) << 4;

    auto compute_stage = [&](int buf, bool /*unused*/) {
        const uint32_t sb = sbase + buf * STAGE_B;
#pragma unroll
        for (int t = 0; t < 3; ++t) {
            const uint32_t Ab = sb + ((t == 2) ? 16384u : 0u);
            const uint32_t Bb = sb + 32768u + ((t == 1) ? 16384u : 0u);
#pragma unroll
            for (int ks = 0; ks < 4; ++ks) {
                const int kb = ks << 5;   // k0*2 bytes (k0 = ks*16)
                uint32_t a[4][4], b[2][4];
#pragma unroll
                for (int mi = 0; mi < 4; ++mi) {
                    uint32_t off = (uint32_t)((wm*64 + mi*16 + rowA) * 128 + kb + kselA);
                    ldm4(a[mi], Ab + SWZ128(off));
                }
#pragma unroll
                for (int nb = 0; nb < 2; ++nb) {
                    uint32_t off = (uint32_t)((wn*32 + nb*16 + rowB) * 128 + kb + kselB);
                    ldm4(b[nb], Bb + SWZ128(off));
                }
#pragma unroll
                for (int mi = 0; mi < 4; ++mi)
#pragma unroll
                    for (int ni = 0; ni < 4; ++ni)
                        mma16816(acc[mi][ni], a[mi],
                                 b[ni >> 1][(ni & 1) * 2], b[ni >> 1][(ni & 1) * 2 + 1]);
            }
        }
    };

    load_stage(0, 0);
    for (int c = 0; c < nch; ++c) {
        const bool more = (c + 1) < nch;
        if (more) load_stage(c + 1, (c + 1) & 1);
        if (more) { CP_WAIT1(); } else { CP_WAIT0(); }
        __syncthreads();
        compute_stage(c & 1, more);
        __syncthreads();
    }

    // ---- epilogue: lane l: rows (l>>2), (l>>2)+8; cols (l&3)*2, +1
    const int er = lid >> 2;
    const int ec = (lid & 3) * 2;
#pragma unroll
    for (int mi = 0; mi < 4; ++mi) {
#pragma unroll
        for (int half = 0; half < 2; ++half) {
            const int gm = m0 + wm*64 + mi*16 + er + half*8;
            if (gm >= M) continue;
#pragma unroll
            for (int ni = 0; ni < 4; ++ni) {
                const int gn = n0 + wn*32 + ni*8 + ec;
                float v0 = acc[mi][ni][half*2 + 0];
                float v1 = acc[mi][ni][half*2 + 1];
                if (EPI == 0) {
                    float2 r; r.x = v0; r.y = v1;
                    *reinterpret_cast<float2*>(C + (size_t)gm*N + gn) = r;
                } else if (EPI == 1) {
                    float2 r; r.x = v0 + bias[gn]; r.y = v1 + bias[gn + 1];
                    *reinterpret_cast<float2*>(C + (size_t)gm*N + gn) = r;
                } else {
                    const size_t o = (size_t)gm*N + gn;
                    float g0 = sigmoidf_(v0 + bias[gn])     * aux[o];
                    float g1 = sigmoidf_(v1 + bias[gn + 1]) * aux[o + 1];
                    __nv_bfloat16 h0, l0, h1, l1;
                    split2(g0, h0, l0); split2(g1, h1, l1);
                    __nv_bfloat162 ph; ph.x = h0; ph.y = h1;
                    __nv_bfloat162 pl; pl.x = l0; pl.y = l1;
                    *reinterpret_cast<__nv_bfloat162*>(Ch + o) = ph;
                    *reinterpret_cast<__nv_bfloat162*>(Cl + o) = pl;
                }
            }
        }
    }
}

// ===========================================================================
// K4: D2[bn,j] = imgC[bn,j,:] . u[bn,:]
// ===========================================================================
__global__ void d2_kernel()
{
    int row = blockIdx.x, bn = row / PDIM, tid = threadIdx.x;
    float p = g_imgC[(size_t)row*RELC + tid] * g_u[bn*RELC + tid];
    __shared__ float sr[8];
#pragma unroll
    for (int off = 16; off; off >>= 1) p += __shfl_xor_sync(0xffffffffu, p, off);
    if ((tid & 31) == 0) sr[tid >> 5] = p;
    __syncthreads();
    if (tid == 0) {
        float s = 0.f;
#pragma unroll
        for (int k = 0; k < 8; ++k) s += sr[k];
        g_D2[row] = s;
    }
}

// ===========================================================================
// K5: per (bn,i): rw softmax -> gw softmax (cat never materialized)
// ===========================================================================
__global__ void gw_kernel()
{
    int blk = blockIdx.x;
    int bn = blk / PDIM, i = blk % PDIM;
    int b = bn / NR, m = bn % NR;
    int tid = threadIdx.x;
    int w = tid >> 5, lane = tid & 31;
    __shared__ float sL[PDIM], sD[PDIM], sred[2];
    const float* vv = g_v + bn*RELC;
    const float* uu = g_u + bn*RELC;

    for (int j = w; j < PDIM; j += 4) {
        int R  = m*(PDIM*PDIM) + i*PDIM + j;
        int si = R / (NR*PDIM);
        size_t rowbase = ((size_t)b*PDIM*PDIM + (size_t)si*PDIM + j) * RELC;
        const float* rs = g_relS + rowbase;
        const float* rc = g_relC + rowbase;
        float s1 = 0.f, s2 = 0.f;
        for (int c = lane; c < RELC; c += 32) { s1 += rs[c]*vv[c]; s2 += rc[c]*uu[c]; }
#pragma unroll
        for (int off = 16; off; off >>= 1) {
            s1 += __shfl_xor_sync(0xffffffffu, s1, off);
            s2 += __shfl_xor_sync(0xffffffffu, s2, off);
        }
        if (lane == 0) { sL[j] = s1; sD[j] = s2; }
    }
    __syncthreads();
    if (tid == 0) { float mx = -1e30f; for (int j=0;j<PDIM;++j) mx = fmaxf(mx, sL[j]); sred[0] = mx; }
    __syncthreads();
    if (tid < PDIM) sL[tid] = __expf(sL[tid] - sred[0]);
    __syncthreads();
    if (tid == 0) { float s = 0.f; for (int j=0;j<PDIM;++j) s += sL[j]; sred[1] = 1.0f/s; }
    __syncthreads();
    if (tid < PDIM) sL[tid] = sL[tid]*sred[1]*sD[tid] + g_D2[bn*PDIM + tid];
    __syncthreads();
    if (tid == 0) { float mx = -1e30f; for (int j=0;j<PDIM;++j) mx = fmaxf(mx, sL[j]); sred[0] = mx; }
    __syncthreads();
    if (tid < PDIM) sL[tid] = __expf(sL[tid] - sred[0]);
    __syncthreads();
    if (tid == 0) { float s = 0.f; for (int j=0;j<PDIM;++j) s += sL[j]; sred[1] = 1.0f/s; }
    __syncthreads();
    if (tid < PDIM) g_gw[(size_t)blk*PDIM + tid] = sL[tid]*sred[1];
}

// ===========================================================================
// K6: img_ws + assemble cii (fp32) + bf16 split of cii
// ===========================================================================
__global__ void imgws_kernel(const float* __restrict__ img)
{
    int chunk = blockIdx.x, bn = blockIdx.y, tid = threadIdx.x;
    __shared__ float sg[PDIM*PDIM];
    for (int t = tid; t < PDIM*PDIM; t += 256) sg[t] = g_gw[(size_t)bn*PDIM*PDIM + t];
    __syncthreads();

    int f = chunk*256 + tid;
    float acc[PDIM];
#pragma unroll
    for (int i = 0; i < PDIM; ++i) acc[i] = 0.f;
    const float* ib = img + (size_t)bn*PDIM*IMGF + f;
#pragma unroll 4
    for (int j = 0; j < PDIM; ++j) {
        float vj = ib[(size_t)j*IMGF];
#pragma unroll
        for (int i = 0; i < PDIM; ++i) acc[i] += sg[i*PDIM + j] * vj;
    }
    size_t cb = (size_t)bn*PDIM*F2 + f;
#pragma unroll
    for (int i = 0; i < PDIM; ++i) {
        float iv = ib[(size_t)i*IMGF];
        size_t o0 = cb + (size_t)i*F2;
        size_t o1 = o0 + IMGF;
        g_cii[o0] = iv;
        g_cii[o1] = acc[i];
        __nv_bfloat16 h, l;
        split2(iv, h, l);     g_cAh[o0] = h; g_cAl[o0] = l;
        split2(acc[i], h, l); g_cAh[o1] = h; g_cAl[o1] = l;
    }
}

// ===========================================================================
// Launch
// ===========================================================================
extern "C" void kernel_launch(void* const* d_in, const int* in_sizes, int n_in,
                              void* d_out, int out_size)
{
    const float* relation = (const float*)d_in[0];
    const float* img      = (const float*)d_in[1];
    const float* ques     = (const float*)d_in[2];
    const float* Wcr      = (const float*)d_in[3];
    const float* bcr      = (const float*)d_in[4];
    const float* Wq       = (const float*)d_in[5];
    const float* bq       = (const float*)d_in[6];
    const float* Wrw      = (const float*)d_in[7];
    const float* Wc       = (const float*)d_in[9];
    const float* bc       = (const float*)d_in[10];
    const float* Wg       = (const float*)d_in[11];
    const float* Ww       = (const float*)d_in[13];
    const float* bw       = (const float*)d_in[14];
    const float* Wi       = (const float*)d_in[15];
    const float* bi       = (const float*)d_in[16];
    float* out = (float*)d_out;

    cudaFuncSetAttribute(hgemm<0>, cudaFuncAttributeMaxDynamicSharedMemorySize, HG_SMEM);
    cudaFuncSetAttribute(hgemm<1>, cudaFuncAttributeMaxDynamicSharedMemorySize, HG_SMEM);
    cudaFuncSetAttribute(hgemm<2>, cudaFuncAttributeMaxDynamicSharedMemorySize, HG_SMEM);

    float *p_relC, *p_imgC, *p_cii;
    __nv_bfloat16 *p_rSh,*p_rSl,*p_iAh,*p_iAl,*p_cAh,*p_cAl,*p_gAh,*p_gAl;
    __nv_bfloat16 *p_B1h,*p_B1l,*p_B2h,*p_B2l,*p_Bwh,*p_Bwl,*p_Bih,*p_Bil;
    cudaGetSymbolAddress((void**)&p_relC, g_relC);
    cudaGetSymbolAddress((void**)&p_imgC, g_imgC);
    cudaGetSymbolAddress((void**)&p_cii,  g_cii);
    cudaGetSymbolAddress((void**)&p_rSh, g_rSh); cudaGetSymbolAddress((void**)&p_rSl, g_rSl);
    cudaGetSymbolAddress((void**)&p_iAh, g_iAh); cudaGetSymbolAddress((void**)&p_iAl, g_iAl);
    cudaGetSymbolAddress((void**)&p_cAh, g_cAh); cudaGetSymbolAddress((void**)&p_cAl, g_cAl);
    cudaGetSymbolAddress((void**)&p_gAh, g_gAh); cudaGetSymbolAddress((void**)&p_gAl, g_gAl);
    cudaGetSymbolAddress((void**)&p_B1h, g_B1h); cudaGetSymbolAddress((void**)&p_B1l, g_B1l);
    cudaGetSymbolAddress((void**)&p_B2h, g_B2h); cudaGetSymbolAddress((void**)&p_B2l, g_B2l);
    cudaGetSymbolAddress((void**)&p_Bwh, g_Bwh); cudaGetSymbolAddress((void**)&p_Bwl, g_Bwl);
    cudaGetSymbolAddress((void**)&p_Bih, g_Bih); cudaGetSymbolAddress((void**)&p_Bil, g_Bil);

    // 1. relS (fp32 + split)
    rels_kernel<<<RELROWS, RELC>>>(relation, Wcr, bcr);
    // 2. question vectors
    ques_kernel<<<BN, RELC>>>(ques, Wq, bq, Wrw, Wg);
    // 3. operand conversions
    split_kernel<<<1024, 256>>>(img, (size_t)ROWS*IMGF, p_iAh, p_iAl);
    tsplit_kernel<<<dim3(RELC/32, RELC/32), dim3(32,8)>>>(Wc, RELC, RELC, p_B1h, p_B1l);
    tsplit_kernel<<<dim3(RELC/32, IMGF/32), dim3(32,8)>>>(Wc + RELC*RELC, IMGF, RELC, p_B2h, p_B2l);
    tsplit_kernel<<<dim3(F2/32, F2/32),    dim3(32,8)>>>(Ww, F2, F2, p_Bwh, p_Bwl);
    tsplit_kernel<<<dim3(IMGF/32, F2/32),  dim3(32,8)>>>(Wi, F2, IMGF, p_Bih, p_Bil);
    // 4. relC = relS @ Wc1   (M=5184, N=256, K=256)
    hgemm<0><<<dim3(RELC/128, (RELROWS+127)/128), 256, HG_SMEM>>>(
        RELROWS, RELC, RELC, p_rSh, p_rSl, p_B1h, p_B1l, nullptr, nullptr, p_relC, nullptr, nullptr);
    // 5. imgC = img @ Wc2 + bc  (M=1440, N=256, K=2048)
    hgemm<1><<<dim3(RELC/128, (ROWS+127)/128), 256, HG_SMEM>>>(
        ROWS, RELC, IMGF, p_iAh, p_iAl, p_B2h, p_B2l, bc, nullptr, p_imgC, nullptr, nullptr);
    // 6. D2
    d2_kernel<<<ROWS, RELC>>>();
    // 7. attention weights
    gw_kernel<<<ROWS, 128>>>();
    // 8. img_ws + cii (+ split)
    imgws_kernel<<<dim3(IMGF/256, BN), 256>>>(img);
    // 9. gated = sigmoid(cii@Ww + bw)*cii -> bf16 split   (M=1440, N=4096, K=4096)
    hgemm<2><<<dim3(F2/128, (ROWS+127)/128), 256, HG_SMEM>>>(
        ROWS, F2, F2, p_cAh, p_cAl, p_Bwh, p_Bwl, bw, p_cii, nullptr, p_gAh, p_gAl);
    // 10. out = gated @ Wi + bi  (M=1440, N=2048, K=4096)
    hgemm<1><<<dim3(IMGF/128, (ROWS+127)/128), 256, HG_SMEM>>>(
        ROWS, IMGF, F2, p_gAh, p_gAl, p_Bih, p_Bil, bi, nullptr, out, nullptr, nullptr);
}

// round 6
// speedup vs baseline: 2.4963x; 1.0692x over previous
#include <cuda_runtime.h>
#include <cuda_bf16.h>
#include <cstdint>
#include <cstddef>

// Problem constants
#define PDIM 36
#define BB 4
#define NR 10
#define BN 40
#define RELD 7
#define RELC 256
#define LSTM 512
#define IMGF 2048
#define ROWS (BN*PDIM)          // 1440
#define RELROWS (BB*PDIM*PDIM)  // 5184
#define F2 (2*IMGF)             // 4096

// ===========================================================================
// Helpers
// ===========================================================================
__device__ __forceinline__ uint32_t smem_u32(const void* p) {
    uint32_t a;
    asm("{ .reg .u64 t; cvta.to.shared.u64 t, %1; cvt.u32.u64 %0, t; }" : "=r"(a) : "l"(p));
    return a;
}
__device__ __forceinline__ float sigmoidf_(float x) { return 1.0f / (1.0f + __expf(-x)); }
__device__ __forceinline__ void split2(float x, __nv_bfloat16& h, __nv_bfloat16& l) {
    h = __float2bfloat16(x);
    l = __float2bfloat16(x - __bfloat162float(h));
}
#define SWZ128(off) ((off) ^ (((off) >> 3) & 0x70))

__device__ __forceinline__ void cp_async16(uint32_t dst, const void* src, int szbytes) {
    asm volatile("cp.async.cg.shared.global [%0], [%1], 16, %2;"
                 :: "r"(dst), "l"(src), "r"(szbytes) : "memory");
}
#define CP_COMMIT() asm volatile("cp.async.commit_group;" ::: "memory")
#define CP_WAIT1()  asm volatile("cp.async.wait_group 1;" ::: "memory")
#define CP_WAIT0()  asm volatile("cp.async.wait_group 0;" ::: "memory")

__device__ __forceinline__ void ldm4(uint32_t* r, uint32_t a) {
    asm volatile("ldmatrix.sync.aligned.m8n8.x4.shared.b16 {%0,%1,%2,%3}, [%4];"
                 : "=r"(r[0]), "=r"(r[1]), "=r"(r[2]), "=r"(r[3]) : "r"(a));
}
__device__ __forceinline__ void mma16816(float* c, const uint32_t* a, uint32_t b0, uint32_t b1) {
    asm volatile("mma.sync.aligned.m16n8k16.row.col.f32.bf16.bf16.f32 "
                 "{%0,%1,%2,%3}, {%4,%5,%6,%7}, {%8,%9}, {%0,%1,%2,%3};"
                 : "+f"(c[0]), "+f"(c[1]), "+f"(c[2]), "+f"(c[3])
                 : "r"(a[0]), "r"(a[1]), "r"(a[2]), "r"(a[3]), "r"(b0), "r"(b1));
}

// ===========================================================================
// Scratch (device globals; no allocations allowed)
// ===========================================================================
__device__ float g_relS [RELROWS*RELC];
__device__ float g_relC [RELROWS*RELC];
__device__ float g_v    [BN*RELC];
__device__ float g_u    [BN*RELC];
__device__ float g_imgC [ROWS*RELC];
__device__ float g_D2   [ROWS];
__device__ float g_gw   [ROWS*PDIM];
__device__ float g_cii  [ROWS*F2];
// bf16 hi/lo operand splits
__device__ __nv_bfloat16 g_rSh[RELROWS*RELC], g_rSl[RELROWS*RELC];
__device__ __nv_bfloat16 g_iAh[ROWS*IMGF],    g_iAl[ROWS*IMGF];
__device__ __nv_bfloat16 g_cAh[(size_t)ROWS*F2], g_cAl[(size_t)ROWS*F2];
__device__ __nv_bfloat16 g_gAh[(size_t)ROWS*F2], g_gAl[(size_t)ROWS*F2];
__device__ __nv_bfloat16 g_B1h[RELC*RELC],    g_B1l[RELC*RELC];
__device__ __nv_bfloat16 g_B2h[RELC*IMGF],    g_B2l[RELC*IMGF];
__device__ __nv_bfloat16 g_Bwh[(size_t)F2*F2],   g_Bwl[(size_t)F2*F2];
__device__ __nv_bfloat16 g_Bih[(size_t)IMGF*F2], g_Bil[(size_t)IMGF*F2];

// ===========================================================================
// K1: relS = sigmoid(relation @ Wcr + bcr) + bf16 split
// ===========================================================================
__global__ void rels_kernel(const float* __restrict__ relation,
                            const float* __restrict__ Wcr,
                            const float* __restrict__ bcr)
{
    int r = blockIdx.x, c = threadIdx.x;
    __shared__ float rd[RELD];
    if (c < RELD) rd[c] = relation[r*RELD + c];
    __syncthreads();
    float acc = bcr[c];
#pragma unroll
    for (int d = 0; d < RELD; ++d) acc += rd[d] * Wcr[d*RELC + c];
    float s = sigmoidf_(acc);
    size_t idx = (size_t)r*RELC + c;
    g_relS[idx] = s;
    __nv_bfloat16 h, l; split2(s, h, l);
    g_rSh[idx] = h; g_rSl[idx] = l;
}

// ===========================================================================
// K2: question vectors
// ===========================================================================
__global__ void ques_kernel(const float* __restrict__ ques,
                            const float* __restrict__ Wq,
                            const float* __restrict__ bq,
                            const float* __restrict__ Wrw,
                            const float* __restrict__ Wg)
{
    int bn = blockIdx.x, c = threadIdx.x;
    __shared__ float q[LSTM];
    q[c] = ques[bn*LSTM + c];
    q[c + 256] = ques[bn*LSTM + c + 256];
    __syncthreads();
    float acc = bq[c];
    for (int k = 0; k < LSTM; ++k) acc += q[k] * Wq[k*RELC + c];
    float s = sigmoidf_(acc);
    g_v[bn*RELC + c] = s * Wrw[c];
    g_u[bn*RELC + c] = s * Wg[c];
}

// ===========================================================================
// K3 (merged): img bf16 split + all 4 weight transpose-splits.
// Blocks: [0,2048) img grid-stride; then tsplit jobs (homogeneous per block).
// ===========================================================================
__global__ void convert_all(const float* __restrict__ img,
                            const float* __restrict__ Wc,
                            const float* __restrict__ Ww,
                            const float* __restrict__ Wi)
{
    int b = blockIdx.x;
    if (b < 2048) {
        size_t n = (size_t)ROWS*IMGF;
        for (size_t i = (size_t)b*256 + threadIdx.x; i < n; i += (size_t)2048*256) {
            __nv_bfloat16 h, l; split2(img[i], h, l);
            g_iAh[i] = h; g_iAl[i] = l;
        }
        return;
    }
    b -= 2048;
    const float* W; int K, N; __nv_bfloat16 *Bh, *Bl; int bx, by;
    if (b < 64)             { W = Wc;             K = RELC; N = RELC; Bh = g_B1h; Bl = g_B1l; bx = b % 8;   by = b / 8; }
    else if (b < 576)       { b -= 64;  W = Wc + RELC*RELC; K = IMGF; N = RELC; Bh = g_B2h; Bl = g_B2l; bx = b % 8;   by = b / 8; }
    else if (b < 576+16384) { b -= 576; W = Ww;   K = F2;   N = F2;   Bh = g_Bwh; Bl = g_Bwl; bx = b % 128; by = b / 128; }
    else                    { b -= 16960; W = Wi; K = F2;   N = IMGF; Bh = g_Bih; Bl = g_Bil; bx = b % 64;  by = b / 64; }

    __shared__ float tile[32][33];
    int tx = threadIdx.x & 31, ty = threadIdx.x >> 5;
    int n0 = bx * 32, k0 = by * 32;
#pragma unroll
    for (int r = 0; r < 4; ++r)
        tile[ty + r*8][tx] = W[(size_t)(k0 + ty + r*8) * N + n0 + tx];
    __syncthreads();
#pragma unroll
    for (int r = 0; r < 4; ++r) {
        int n = n0 + ty + r*8, k = k0 + tx;
        float v = tile[tx][ty + r*8];
        __nv_bfloat16 h, l; split2(v, h, l);
        Bh[(size_t)n*K + k] = h;
        Bl[(size_t)n*K + k] = l;
    }
}

// ===========================================================================
// bf16-split GEMM via mma.sync (HMMA): C[M,N] = (Ah+Al)@(Bh+Bl)^T
// CTA tile 128x128, BK=64 bf16 (128B SW128 rows), 8 warps 2x4 (warp 64x32),
// 3-stage cp.async pipeline, one __syncthreads per chunk, fragment reuse
// across the 3 split terms: AhBh + AhBl + AlBh.
// EPI: 0 plain fp32, 1 +bias fp32, 2 sigmoid(acc+bias)*aux -> bf16 hi/lo
// ===========================================================================
#define STAGE_B 65536          // 4 tiles x 16KB
#define NSTAGE 3
#define HG_SMEM (NSTAGE*STAGE_B)

template<int EPI>
__global__ __launch_bounds__(256, 1)
void hgemm(int M, int N, int K,
           const __nv_bfloat16* __restrict__ Ah, const __nv_bfloat16* __restrict__ Al,
           const __nv_bfloat16* __restrict__ Bh, const __nv_bfloat16* __restrict__ Bl,
           const float* __restrict__ bias, const float* __restrict__ aux,
           float* __restrict__ C,
           __nv_bfloat16* __restrict__ Ch, __nv_bfloat16* __restrict__ Cl)
{
    extern __shared__ char sm[];
    const uint32_t sbase = smem_u32(sm);

    const int tid = threadIdx.x;
    const int lid = tid & 31;
    const int wid = tid >> 5;
    const int wm = wid & 1;        // M dir (64 rows each)
    const int wn = wid >> 1;       // N dir (32 cols each)
    const int m0 = blockIdx.y * 128;
    const int n0 = blockIdx.x * 128;

    float acc[4][4][4];
#pragma unroll
    for (int i = 0; i < 4; ++i)
#pragma unroll
        for (int j = 0; j < 4; ++j)
#pragma unroll
            for (int e = 0; e < 4; ++e) acc[i][j][e] = 0.f;

    // loader mapping: 2 threads per row, 4 x 16B segments each
    const int lrow = tid >> 1;
    const int lseg = (tid & 1) * 4;
    const int gmrow = m0 + lrow;
    const int a_ok = (gmrow < M) ? 16 : 0;
    const size_t aoff = (size_t)(a_ok ? gmrow : 0) * K;
    const size_t boff = (size_t)(n0 + lrow) * K;

    const int nch = K >> 6;

    auto load_stage = [&](int c, int buf) {
        const int k0 = c << 6;
        const uint32_t sb = sbase + buf * STAGE_B;
        const char* pAh = (const char*)(Ah + aoff + k0);
        const char* pAl = (const char*)(Al + aoff + k0);
        const char* pBh = (const char*)(Bh + boff + k0);
        const char* pBl = (const char*)(Bl + boff + k0);
#pragma unroll
        for (int s = 0; s < 4; ++s) {
            const int colb = (lseg + s) * 16;
            const uint32_t sw = SWZ128((uint32_t)(lrow * 128 + colb));
            cp_async16(sb + sw,         pAh + colb, a_ok);
            cp_async16(sb + 16384 + sw, pAl + colb, a_ok);
            cp_async16(sb + 32768 + sw, pBh + colb, 16);
            cp_async16(sb + 49152 + sw, pBl + colb, 16);
        }
        CP_COMMIT();
    };

    // fragment lane components
    const int matA  = lid >> 3;
    const int rowA  = (lid & 7) + ((matA & 1) << 3);
    const int kselA = (matA >> 1) << 4;
    const int rowB  = (lid & 7) + ((matA >> 1) << 3);
    const int kselB = (matA & 1) << 4;

    auto compute_stage = [&](int buf) {
        const uint32_t sb = sbase + buf * STAGE_B;
#pragma unroll
        for (int ks = 0; ks < 4; ++ks) {
            const int kb = ks << 5;
            uint32_t ah[4][4], al[4][4], bh[2][4], bl[2][4];
#pragma unroll
            for (int mi = 0; mi < 4; ++mi) {
                uint32_t off = SWZ128((uint32_t)((wm*64 + mi*16 + rowA) * 128 + kb + kselA));
                ldm4(ah[mi], sb + off);
                ldm4(al[mi], sb + 16384u + off);
            }
#pragma unroll
            for (int nb = 0; nb < 2; ++nb) {
                uint32_t off = SWZ128((uint32_t)((wn*32 + nb*16 + rowB) * 128 + kb + kselB));
                ldm4(bh[nb], sb + 32768u + off);
                ldm4(bl[nb], sb + 49152u + off);
            }
#pragma unroll
            for (int mi = 0; mi < 4; ++mi)
#pragma unroll
                for (int ni = 0; ni < 4; ++ni) {
                    uint32_t h0 = bh[ni >> 1][(ni & 1) * 2], h1 = bh[ni >> 1][(ni & 1) * 2 + 1];
                    uint32_t l0 = bl[ni >> 1][(ni & 1) * 2], l1 = bl[ni >> 1][(ni & 1) * 2 + 1];
                    mma16816(acc[mi][ni], ah[mi], h0, h1);
                    mma16816(acc[mi][ni], ah[mi], l0, l1);
                    mma16816(acc[mi][ni], al[mi], h0, h1);
                }
        }
    };

    load_stage(0, 0);
    if (nch > 1) load_stage(1, 1);
    for (int c = 0; c < nch; ++c) {
        if (c + 1 < nch) { CP_WAIT1(); } else { CP_WAIT0(); }
        __syncthreads();                       // data ready + prev compute done
        if (c + 2 < nch) load_stage(c + 2, (c + 2) % NSTAGE);
        compute_stage(c % NSTAGE);
    }

    // epilogue
    const int er = lid >> 2;
    const int ec = (lid & 3) * 2;
#pragma unroll
    for (int mi = 0; mi < 4; ++mi) {
#pragma unroll
        for (int half = 0; half < 2; ++half) {
            const int gm = m0 + wm*64 + mi*16 + er + half*8;
            if (gm >= M) continue;
#pragma unroll
            for (int ni = 0; ni < 4; ++ni) {
                const int gn = n0 + wn*32 + ni*8 + ec;
                float v0 = acc[mi][ni][half*2 + 0];
                float v1 = acc[mi][ni][half*2 + 1];
                if (EPI == 0) {
                    float2 r; r.x = v0; r.y = v1;
                    *reinterpret_cast<float2*>(C + (size_t)gm*N + gn) = r;
                } else if (EPI == 1) {
                    float2 r; r.x = v0 + bias[gn]; r.y = v1 + bias[gn + 1];
                    *reinterpret_cast<float2*>(C + (size_t)gm*N + gn) = r;
                } else {
                    const size_t o = (size_t)gm*N + gn;
                    float g0 = sigmoidf_(v0 + bias[gn])     * aux[o];
                    float g1 = sigmoidf_(v1 + bias[gn + 1]) * aux[o + 1];
                    __nv_bfloat16 h0, l0, h1, l1;
                    split2(g0, h0, l0); split2(g1, h1, l1);
                    __nv_bfloat162 ph; ph.x = h0; ph.y = h1;
                    __nv_bfloat162 pl; pl.x = l0; pl.y = l1;
                    *reinterpret_cast<__nv_bfloat162*>(Ch + o) = ph;
                    *reinterpret_cast<__nv_bfloat162*>(Cl + o) = pl;
                }
            }
        }
    }
}

// ===========================================================================
// K4: D2[bn,j] = imgC[bn,j,:] . u[bn,:]
// ===========================================================================
__global__ void d2_kernel()
{
    int row = blockIdx.x, bn = row / PDIM, tid = threadIdx.x;
    float p = g_imgC[(size_t)row*RELC + tid] * g_u[bn*RELC + tid];
    __shared__ float sr[8];
#pragma unroll
    for (int off = 16; off; off >>= 1) p += __shfl_xor_sync(0xffffffffu, p, off);
    if ((tid & 31) == 0) sr[tid >> 5] = p;
    __syncthreads();
    if (tid == 0) {
        float s = 0.f;
#pragma unroll
        for (int k = 0; k < 8; ++k) s += sr[k];
        g_D2[row] = s;
    }
}

// ===========================================================================
// K5: per (bn,i): rw softmax -> gw softmax (cat never materialized)
// ===========================================================================
__global__ void gw_kernel()
{
    int blk = blockIdx.x;
    int bn = blk / PDIM, i = blk % PDIM;
    int b = bn / NR, m = bn % NR;
    int tid = threadIdx.x;
    int w = tid >> 5, lane = tid & 31;
    __shared__ float sL[PDIM], sD[PDIM], sred[2];
    const float* vv = g_v + bn*RELC;
    const float* uu = g_u + bn*RELC;

    for (int j = w; j < PDIM; j += 4) {
        int R  = m*(PDIM*PDIM) + i*PDIM + j;
        int si = R / (NR*PDIM);
        size_t rowbase = ((size_t)b*PDIM*PDIM + (size_t)si*PDIM + j) * RELC;
        const float* rs = g_relS + rowbase;
        const float* rc = g_relC + rowbase;
        float s1 = 0.f, s2 = 0.f;
        for (int c = lane; c < RELC; c += 32) { s1 += rs[c]*vv[c]; s2 += rc[c]*uu[c]; }
#pragma unroll
        for (int off = 16; off; off >>= 1) {
            s1 += __shfl_xor_sync(0xffffffffu, s1, off);
            s2 += __shfl_xor_sync(0xffffffffu, s2, off);
        }
        if (lane == 0) { sL[j] = s1; sD[j] = s2; }
    }
    __syncthreads();
    if (tid == 0) { float mx = -1e30f; for (int j=0;j<PDIM;++j) mx = fmaxf(mx, sL[j]); sred[0] = mx; }
    __syncthreads();
    if (tid < PDIM) sL[tid] = __expf(sL[tid] - sred[0]);
    __syncthreads();
    if (tid == 0) { float s = 0.f; for (int j=0;j<PDIM;++j) s += sL[j]; sred[1] = 1.0f/s; }
    __syncthreads();
    if (tid < PDIM) sL[tid] = sL[tid]*sred[1]*sD[tid] + g_D2[bn*PDIM + tid];
    __syncthreads();
    if (tid == 0) { float mx = -1e30f; for (int j=0;j<PDIM;++j) mx = fmaxf(mx, sL[j]); sred[0] = mx; }
    __syncthreads();
    if (tid < PDIM) sL[tid] = __expf(sL[tid] - sred[0]);
    __syncthreads();
    if (tid == 0) { float s = 0.f; for (int j=0;j<PDIM;++j) s += sL[j]; sred[1] = 1.0f/s; }
    __syncthreads();
    if (tid < PDIM) g_gw[(size_t)blk*PDIM + tid] = sL[tid]*sred[1];
}

// ===========================================================================
// K6: img_ws + assemble cii (fp32) + bf16 split of cii
// ===========================================================================
__global__ void imgws_kernel(const float* __restrict__ img)
{
    int chunk = blockIdx.x, bn = blockIdx.y, tid = threadIdx.x;
    __shared__ float sg[PDIM*PDIM];
    for (int t = tid; t < PDIM*PDIM; t += 256) sg[t] = g_gw[(size_t)bn*PDIM*PDIM + t];
    __syncthreads();

    int f = chunk*256 + tid;
    float acc[PDIM];
#pragma unroll
    for (int i = 0; i < PDIM; ++i) acc[i] = 0.f;
    const float* ib = img + (size_t)bn*PDIM*IMGF + f;
#pragma unroll 4
    for (int j = 0; j < PDIM; ++j) {
        float vj = ib[(size_t)j*IMGF];
#pragma unroll
        for (int i = 0; i < PDIM; ++i) acc[i] += sg[i*PDIM + j] * vj;
    }
    size_t cb = (size_t)bn*PDIM*F2 + f;
#pragma unroll
    for (int i = 0; i < PDIM; ++i) {
        float iv = ib[(size_t)i*IMGF];
        size_t o0 = cb + (size_t)i*F2;
        size_t o1 = o0 + IMGF;
        g_cii[o0] = iv;
        g_cii[o1] = acc[i];
        __nv_bfloat16 h, l;
        split2(iv, h, l);     g_cAh[o0] = h; g_cAl[o0] = l;
        split2(acc[i], h, l); g_cAh[o1] = h; g_cAl[o1] = l;
    }
}

// ===========================================================================
// Launch
// ===========================================================================
extern "C" void kernel_launch(void* const* d_in, const int* in_sizes, int n_in,
                              void* d_out, int out_size)
{
    const float* relation = (const float*)d_in[0];
    const float* img      = (const float*)d_in[1];
    const float* ques     = (const float*)d_in[2];
    const float* Wcr      = (const float*)d_in[3];
    const float* bcr      = (const float*)d_in[4];
    const float* Wq       = (const float*)d_in[5];
    const float* bq       = (const float*)d_in[6];
    const float* Wrw      = (const float*)d_in[7];
    const float* Wc       = (const float*)d_in[9];
    const float* bc       = (const float*)d_in[10];
    const float* Wg       = (const float*)d_in[11];
    const float* Ww       = (const float*)d_in[13];
    const float* bw       = (const float*)d_in[14];
    const float* Wi       = (const float*)d_in[15];
    const float* bi       = (const float*)d_in[16];
    float* out = (float*)d_out;

    cudaFuncSetAttribute(hgemm<0>, cudaFuncAttributeMaxDynamicSharedMemorySize, HG_SMEM);
    cudaFuncSetAttribute(hgemm<1>, cudaFuncAttributeMaxDynamicSharedMemorySize, HG_SMEM);
    cudaFuncSetAttribute(hgemm<2>, cudaFuncAttributeMaxDynamicSharedMemorySize, HG_SMEM);

    float *p_relC, *p_imgC, *p_cii;
    __nv_bfloat16 *p_rSh,*p_rSl,*p_iAh,*p_iAl,*p_cAh,*p_cAl,*p_gAh,*p_gAl;
    __nv_bfloat16 *p_B1h,*p_B1l,*p_B2h,*p_B2l,*p_Bwh,*p_Bwl,*p_Bih,*p_Bil;
    cudaGetSymbolAddress((void**)&p_relC, g_relC);
    cudaGetSymbolAddress((void**)&p_imgC, g_imgC);
    cudaGetSymbolAddress((void**)&p_cii,  g_cii);
    cudaGetSymbolAddress((void**)&p_rSh, g_rSh); cudaGetSymbolAddress((void**)&p_rSl, g_rSl);
    cudaGetSymbolAddress((void**)&p_iAh, g_iAh); cudaGetSymbolAddress((void**)&p_iAl, g_iAl);
    cudaGetSymbolAddress((void**)&p_cAh, g_cAh); cudaGetSymbolAddress((void**)&p_cAl, g_cAl);
    cudaGetSymbolAddress((void**)&p_gAh, g_gAh); cudaGetSymbolAddress((void**)&p_gAl, g_gAl);
    cudaGetSymbolAddress((void**)&p_B1h, g_B1h); cudaGetSymbolAddress((void**)&p_B1l, g_B1l);
    cudaGetSymbolAddress((void**)&p_B2h, g_B2h); cudaGetSymbolAddress((void**)&p_B2l, g_B2l);
    cudaGetSymbolAddress((void**)&p_Bwh, g_Bwh); cudaGetSymbolAddress((void**)&p_Bwl, g_Bwl);
    cudaGetSymbolAddress((void**)&p_Bih, g_Bih); cudaGetSymbolAddress((void**)&p_Bil, g_Bil);

    // 1. relS (fp32 + split)
    rels_kernel<<<RELROWS, RELC>>>(relation, Wcr, bcr);
    // 2. question vectors
    ques_kernel<<<BN, RELC>>>(ques, Wq, bq, Wrw, Wg);
    // 3. all operand conversions (merged)
    convert_all<<<2048 + 64 + 512 + 16384 + 8192, 256>>>(img, Wc, Ww, Wi);
    // 4. imgC = img @ Wc2 + bc   (M=1440, N=256, K=2048)  <-- profiled slot
    hgemm<1><<<dim3(RELC/128, (ROWS+127)/128), 256, HG_SMEM>>>(
        ROWS, RELC, IMGF, p_iAh, p_iAl, p_B2h, p_B2l, bc, nullptr, p_imgC, nullptr, nullptr);
    // 5. relC = relS @ Wc1   (M=5184, N=256, K=256)
    hgemm<0><<<dim3(RELC/128, (RELROWS+127)/128), 256, HG_SMEM>>>(
        RELROWS, RELC, RELC, p_rSh, p_rSl, p_B1h, p_B1l, nullptr, nullptr, p_relC, nullptr, nullptr);
    // 6. D2
    d2_kernel<<<ROWS, RELC>>>();
    // 7. attention weights
    gw_kernel<<<ROWS, 128>>>();
    // 8. img_ws + cii (+ split)
    imgws_kernel<<<dim3(IMGF/256, BN), 256>>>(img);
    // 9. gated = sigmoid(cii@Ww + bw)*cii -> bf16 split   (M=1440, N=4096, K=4096)
    hgemm<2><<<dim3(F2/128, (ROWS+127)/128), 256, HG_SMEM>>>(
        ROWS, F2, F2, p_cAh, p_cAl, p_Bwh, p_Bwl, bw, p_cii, nullptr, p_gAh, p_gAl);
    // 10. out = gated @ Wi + bi  (M=1440, N=2048, K=4096)
    hgemm<1><<<dim3(IMGF/128, (ROWS+127)/128), 256, HG_SMEM>>>(
        ROWS, IMGF, F2, p_gAh, p_gAl, p_Bih, p_Bil, bi, nullptr, out, nullptr, nullptr);
}

// round 8
// speedup vs baseline: 2.5266x; 1.0121x over previous
#include <cuda_runtime.h>
#include <cuda_bf16.h>
#include <cstdint>
#include <cstddef>

// Problem constants
#define PDIM 36
#define BB 4
#define NR 10
#define BN 40
#define RELD 7
#define RELC 256
#define LSTM 512
#define IMGF 2048
#define ROWS (BN*PDIM)          // 1440
#define RELROWS (BB*PDIM*PDIM)  // 5184
#define F2 (2*IMGF)             // 4096

// ===========================================================================
// Helpers
// ===========================================================================
__device__ __forceinline__ uint32_t smem_u32(const void* p) {
    uint32_t a;
    asm("{ .reg .u64 t; cvta.to.shared.u64 t, %1; cvt.u32.u64 %0, t; }" : "=r"(a) : "l"(p));
    return a;
}
__device__ __forceinline__ float sigmoidf_(float x) { return 1.0f / (1.0f + __expf(-x)); }
__device__ __forceinline__ void split2(float x, __nv_bfloat16& h, __nv_bfloat16& l) {
    h = __float2bfloat16(x);
    l = __float2bfloat16(x - __bfloat162float(h));
}
#define SWZ128(off) ((off) ^ (((off) >> 3) & 0x70))

__device__ __forceinline__ void cp_async16(uint32_t dst, const void* src, int szbytes) {
    asm volatile("cp.async.cg.shared.global [%0], [%1], 16, %2;"
                 :: "r"(dst), "l"(src), "r"(szbytes) : "memory");
}
#define CP_COMMIT() asm volatile("cp.async.commit_group;" ::: "memory")
#define CP_WAIT1()  asm volatile("cp.async.wait_group 1;" ::: "memory")
#define CP_WAIT0()  asm volatile("cp.async.wait_group 0;" ::: "memory")

__device__ __forceinline__ void ldm4(uint32_t* r, uint32_t a) {
    asm volatile("ldmatrix.sync.aligned.m8n8.x4.shared.b16 {%0,%1,%2,%3}, [%4];"
                 : "=r"(r[0]), "=r"(r[1]), "=r"(r[2]), "=r"(r[3]) : "r"(a));
}
__device__ __forceinline__ void mma16816(float* c, const uint32_t* a, uint32_t b0, uint32_t b1) {
    asm volatile("mma.sync.aligned.m16n8k16.row.col.f32.bf16.bf16.f32 "
                 "{%0,%1,%2,%3}, {%4,%5,%6,%7}, {%8,%9}, {%0,%1,%2,%3};"
                 : "+f"(c[0]), "+f"(c[1]), "+f"(c[2]), "+f"(c[3])
                 : "r"(a[0]), "r"(a[1]), "r"(a[2]), "r"(a[3]), "r"(b0), "r"(b1));
}

// ===========================================================================
// Scratch (device globals; no allocations allowed)
// ===========================================================================
__device__ float g_relS [RELROWS*RELC];
__device__ float g_relC [RELROWS*RELC];
__device__ float g_v    [BN*RELC];
__device__ float g_u    [BN*RELC];
__device__ float g_imgC [ROWS*RELC];
__device__ float g_D2   [ROWS];
__device__ float g_gw   [ROWS*PDIM];
__device__ float g_cii  [ROWS*F2];
// bf16 hi/lo operand splits
__device__ __nv_bfloat16 g_rSh[RELROWS*RELC], g_rSl[RELROWS*RELC];
__device__ __nv_bfloat16 g_iAh[ROWS*IMGF],    g_iAl[ROWS*IMGF];
__device__ __nv_bfloat16 g_cAh[(size_t)ROWS*F2], g_cAl[(size_t)ROWS*F2];
__device__ __nv_bfloat16 g_gAh[(size_t)ROWS*F2], g_gAl[(size_t)ROWS*F2];
__device__ __nv_bfloat16 g_B1h[RELC*RELC],    g_B1l[RELC*RELC];
__device__ __nv_bfloat16 g_B2h[RELC*IMGF],    g_B2l[RELC*IMGF];
__device__ __nv_bfloat16 g_Bwh[(size_t)F2*F2],   g_Bwl[(size_t)F2*F2];
__device__ __nv_bfloat16 g_Bih[(size_t)IMGF*F2], g_Bil[(size_t)IMGF*F2];

// ===========================================================================
// K1: relS = sigmoid(relation @ Wcr + bcr) + bf16 split
// ===========================================================================
__global__ void rels_kernel(const float* __restrict__ relation,
                            const float* __restrict__ Wcr,
                            const float* __restrict__ bcr)
{
    int r = blockIdx.x, c = threadIdx.x;
    __shared__ float rd[RELD];
    if (c < RELD) rd[c] = relation[r*RELD + c];
    __syncthreads();
    float acc = bcr[c];
#pragma unroll
    for (int d = 0; d < RELD; ++d) acc += rd[d] * Wcr[d*RELC + c];
    float s = sigmoidf_(acc);
    size_t idx = (size_t)r*RELC + c;
    g_relS[idx] = s;
    __nv_bfloat16 h, l; split2(s, h, l);
    g_rSh[idx] = h; g_rSl[idx] = l;
}

// ===========================================================================
// K2: question vectors
// ===========================================================================
__global__ void ques_kernel(const float* __restrict__ ques,
                            const float* __restrict__ Wq,
                            const float* __restrict__ bq,
                            const float* __restrict__ Wrw,
                            const float* __restrict__ Wg)
{
    int bn = blockIdx.x, c = threadIdx.x;
    __shared__ float q[LSTM];
    q[c] = ques[bn*LSTM + c];
    q[c + 256] = ques[bn*LSTM + c + 256];
    __syncthreads();
    float acc = bq[c];
    for (int k = 0; k < LSTM; ++k) acc += q[k] * Wq[k*RELC + c];
    float s = sigmoidf_(acc);
    g_v[bn*RELC + c] = s * Wrw[c];
    g_u[bn*RELC + c] = s * Wg[c];
}

// ===========================================================================
// K3 (merged): img bf16 split + all 4 weight transpose-splits
// ===========================================================================
__global__ void convert_all(const float* __restrict__ img,
                            const float* __restrict__ Wc,
                            const float* __restrict__ Ww,
                            const float* __restrict__ Wi)
{
    int b = blockIdx.x;
    if (b < 2048) {
        size_t n = (size_t)ROWS*IMGF;
        for (size_t i = (size_t)b*256 + threadIdx.x; i < n; i += (size_t)2048*256) {
            __nv_bfloat16 h, l; split2(img[i], h, l);
            g_iAh[i] = h; g_iAl[i] = l;
        }
        return;
    }
    b -= 2048;
    const float* W; int K, N; __nv_bfloat16 *Bh, *Bl; int bx, by;
    if (b < 64)             { W = Wc;             K = RELC; N = RELC; Bh = g_B1h; Bl = g_B1l; bx = b % 8;   by = b / 8; }
    else if (b < 576)       { b -= 64;  W = Wc + RELC*RELC; K = IMGF; N = RELC; Bh = g_B2h; Bl = g_B2l; bx = b % 8;   by = b / 8; }
    else if (b < 576+16384) { b -= 576; W = Ww;   K = F2;   N = F2;   Bh = g_Bwh; Bl = g_Bwl; bx = b % 128; by = b / 128; }
    else                    { b -= 16960; W = Wi; K = F2;   N = IMGF; Bh = g_Bih; Bl = g_Bil; bx = b % 64;  by = b / 64; }

    __shared__ float tile[32][33];
    int tx = threadIdx.x & 31, ty = threadIdx.x >> 5;
    int n0 = bx * 32, k0 = by * 32;
#pragma unroll
    for (int r = 0; r < 4; ++r)
        tile[ty + r*8][tx] = W[(size_t)(k0 + ty + r*8) * N + n0 + tx];
    __syncthreads();
#pragma unroll
    for (int r = 0; r < 4; ++r) {
        int n = n0 + ty + r*8, k = k0 + tx;
        float v = tile[tx][ty + r*8];
        __nv_bfloat16 h, l; split2(v, h, l);
        Bh[(size_t)n*K + k] = h;
        Bl[(size_t)n*K + k] = l;
    }
}

// ===========================================================================
// bf16-split GEMM tile body (device function).
// CTA tile 128x128, BK=64, 8 warps 2x4, 3-stage cp.async pipeline,
// k-step fragment double-buffering (LDSM prefetch hides latency).
// 3 terms: AhBh + AhBl + AlBh, reordered term-major (no back-to-back RAW).
// ===========================================================================
#define STAGE_B 65536
#define NSTAGE 3
#define HG_SMEM (NSTAGE*STAGE_B)

struct Frags {
    uint32_t ah[4][4];
    uint32_t al[4][4];
    uint32_t bh[2][4];
    uint32_t bl[2][4];
};

template<int EPI>
__device__ __forceinline__ void gemm_tile(
    int M, int N, int K, int m0, int n0,
    const __nv_bfloat16* __restrict__ Ah, const __nv_bfloat16* __restrict__ Al,
    const __nv_bfloat16* __restrict__ Bh, const __nv_bfloat16* __restrict__ Bl,
    const float* __restrict__ bias, const float* __restrict__ aux,
    float* __restrict__ C,
    __nv_bfloat16* __restrict__ Ch, __nv_bfloat16* __restrict__ Cl,
    uint32_t sbase)
{
    const int tid = threadIdx.x;
    const int lid = tid & 31;
    const int wid = tid >> 5;
    const int wm = wid & 1;
    const int wn = wid >> 1;

    float acc[4][4][4];
#pragma unroll
    for (int i = 0; i < 4; ++i)
#pragma unroll
        for (int j = 0; j < 4; ++j)
#pragma unroll
            for (int e = 0; e < 4; ++e) acc[i][j][e] = 0.f;

    // loader mapping
    const int lrow = tid >> 1;
    const int lseg = (tid & 1) * 4;
    const int gmrow = m0 + lrow;
    const int a_ok = (gmrow < M) ? 16 : 0;
    const size_t aoff = (size_t)(a_ok ? gmrow : 0) * K;
    const size_t boff = (size_t)(n0 + lrow) * K;

    const int nch = K >> 6;

    auto load_stage = [&](int c, int buf) {
        const int k0 = c << 6;
        const uint32_t sb = sbase + buf * STAGE_B;
        const char* pAh = (const char*)(Ah + aoff + k0);
        const char* pAl = (const char*)(Al + aoff + k0);
        const char* pBh = (const char*)(Bh + boff + k0);
        const char* pBl = (const char*)(Bl + boff + k0);
#pragma unroll
        for (int s = 0; s < 4; ++s) {
            const int colb = (lseg + s) * 16;
            const uint32_t sw = SWZ128((uint32_t)(lrow * 128 + colb));
            cp_async16(sb + sw,         pAh + colb, a_ok);
            cp_async16(sb + 16384 + sw, pAl + colb, a_ok);
            cp_async16(sb + 32768 + sw, pBh + colb, 16);
            cp_async16(sb + 49152 + sw, pBl + colb, 16);
        }
        CP_COMMIT();
    };

    // fragment lane components
    const int matA  = lid >> 3;
    const int rowA  = (lid & 7) + ((matA & 1) << 3);
    const int kselA = (matA >> 1) << 4;
    const int rowB  = (lid & 7) + ((matA >> 1) << 3);
    const int kselB = (matA & 1) << 4;

    auto load_frags = [&](uint32_t sb, int ks, Frags& F) {
        const int kb = ks << 5;
#pragma unroll
        for (int mi = 0; mi < 4; ++mi) {
            uint32_t off = SWZ128((uint32_t)((wm*64 + mi*16 + rowA) * 128 + kb + kselA));
            ldm4(F.ah[mi], sb + off);
            ldm4(F.al[mi], sb + 16384u + off);
        }
#pragma unroll
        for (int nb = 0; nb < 2; ++nb) {
            uint32_t off = SWZ128((uint32_t)((wn*32 + nb*16 + rowB) * 128 + kb + kselB));
            ldm4(F.bh[nb], sb + 32768u + off);
            ldm4(F.bl[nb], sb + 49152u + off);
        }
    };

    auto mma_all = [&](Frags& F) {
        // term-major: consecutive MMAs hit distinct accumulators (no RAW chains)
#pragma unroll
        for (int mi = 0; mi < 4; ++mi)
#pragma unroll
            for (int ni = 0; ni < 4; ++ni)
                mma16816(acc[mi][ni], F.ah[mi],
                         F.bh[ni >> 1][(ni & 1) * 2], F.bh[ni >> 1][(ni & 1) * 2 + 1]);
#pragma unroll
        for (int mi = 0; mi < 4; ++mi)
#pragma unroll
            for (int ni = 0; ni < 4; ++ni)
                mma16816(acc[mi][ni], F.ah[mi],
                         F.bl[ni >> 1][(ni & 1) * 2], F.bl[ni >> 1][(ni & 1) * 2 + 1]);
#pragma unroll
        for (int mi = 0; mi < 4; ++mi)
#pragma unroll
            for (int ni = 0; ni < 4; ++ni)
                mma16816(acc[mi][ni], F.al[mi],
                         F.bh[ni >> 1][(ni & 1) * 2], F.bh[ni >> 1][(ni & 1) * 2 + 1]);
    };

    load_stage(0, 0);
    if (nch > 1) load_stage(1, 1);
    for (int c = 0; c < nch; ++c) {
        if (c + 1 < nch) { CP_WAIT1(); } else { CP_WAIT0(); }
        __syncthreads();
        if (c + 2 < nch) load_stage(c + 2, (c + 2) % NSTAGE);
        const uint32_t sb = sbase + (c % NSTAGE) * STAGE_B;
        Frags f0, f1;
        load_frags(sb, 0, f0);
#pragma unroll
        for (int ks = 0; ks < 4; ++ks) {
            Frags& cur = (ks & 1) ? f1 : f0;
            Frags& nxt = (ks & 1) ? f0 : f1;
            if (ks < 3) load_frags(sb, ks + 1, nxt);
            mma_all(cur);
        }
    }

    // epilogue
    const int er = lid >> 2;
    const int ec = (lid & 3) * 2;
#pragma unroll
    for (int mi = 0; mi < 4; ++mi) {
#pragma unroll
        for (int half = 0; half < 2; ++half) {
            const int gm = m0 + wm*64 + mi*16 + er + half*8;
            if (gm >= M) continue;
#pragma unroll
            for (int ni = 0; ni < 4; ++ni) {
                const int gn = n0 + wn*32 + ni*8 + ec;
                float v0 = acc[mi][ni][half*2 + 0];
                float v1 = acc[mi][ni][half*2 + 1];
                if (EPI == 0) {
                    float2 r; r.x = v0; r.y = v1;
                    *reinterpret_cast<float2*>(C + (size_t)gm*N + gn) = r;
                } else if (EPI == 1) {
                    float2 r; r.x = v0 + bias[gn]; r.y = v1 + bias[gn + 1];
                    *reinterpret_cast<float2*>(C + (size_t)gm*N + gn) = r;
                } else {
                    const size_t o = (size_t)gm*N + gn;
                    float g0 = sigmoidf_(v0 + bias[gn])     * aux[o];
                    float g1 = sigmoidf_(v1 + bias[gn + 1]) * aux[o + 1];
                    __nv_bfloat16 h0, l0, h1, l1;
                    split2(g0, h0, l0); split2(g1, h1, l1);
                    __nv_bfloat162 ph; ph.x = h0; ph.y = h1;
                    __nv_bfloat162 pl; pl.x = l0; pl.y = l1;
                    *reinterpret_cast<__nv_bfloat162*>(Ch + o) = ph;
                    *reinterpret_cast<__nv_bfloat162*>(Cl + o) = pl;
                }
            }
        }
    }
}

template<int EPI>
__global__ __launch_bounds__(256, 1)
void hgemm(int M, int N, int K,
           const __nv_bfloat16* __restrict__ Ah, const __nv_bfloat16* __restrict__ Al,
           const __nv_bfloat16* __restrict__ Bh, const __nv_bfloat16* __restrict__ Bl,
           const float* __restrict__ bias, const float* __restrict__ aux,
           float* __restrict__ C,
           __nv_bfloat16* __restrict__ Ch, __nv_bfloat16* __restrict__ Cl)
{
    extern __shared__ char sm[];
    gemm_tile<EPI>(M, N, K, blockIdx.y * 128, blockIdx.x * 128,
                   Ah, Al, Bh, Bl, bias, aux, C, Ch, Cl, smem_u32(sm));
}

// Merged launch: blocks [0,24) imgC GEMM (EPI1), [24,106) relC GEMM (EPI0)
__global__ __launch_bounds__(256, 1)
void hgemm_dual(const __nv_bfloat16* __restrict__ iAh, const __nv_bfloat16* __restrict__ iAl,
                const __nv_bfloat16* __restrict__ B2h, const __nv_bfloat16* __restrict__ B2l,
                const float* __restrict__ bc, float* __restrict__ imgC,
                const __nv_bfloat16* __restrict__ rSh, const __nv_bfloat16* __restrict__ rSl,
                const __nv_bfloat16* __restrict__ B1h, const __nv_bfloat16* __restrict__ B1l,
                float* __restrict__ relC)
{
    extern __shared__ char sm[];
    const uint32_t sbase = smem_u32(sm);
    int blk = blockIdx.x;
    if (blk < 24) {
        gemm_tile<1>(ROWS, RELC, IMGF, (blk >> 1) * 128, (blk & 1) * 128,
                     iAh, iAl, B2h, B2l, bc, nullptr, imgC, nullptr, nullptr, sbase);
    } else {
        int idx = blk - 24;
        gemm_tile<0>(RELROWS, RELC, RELC, (idx >> 1) * 128, (idx & 1) * 128,
                     rSh, rSl, B1h, B1l, nullptr, nullptr, relC, nullptr, nullptr, sbase);
    }
}

// ===========================================================================
// K4: D2[bn,j] = imgC[bn,j,:] . u[bn,:]
// ===========================================================================
__global__ void d2_kernel()
{
    int row = blockIdx.x, bn = row / PDIM, tid = threadIdx.x;
    float p = g_imgC[(size_t)row*RELC + tid] * g_u[bn*RELC + tid];
    __shared__ float sr[8];
#pragma unroll
    for (int off = 16; off; off >>= 1) p += __shfl_xor_sync(0xffffffffu, p, off);
    if ((tid & 31) == 0) sr[tid >> 5] = p;
    __syncthreads();
    if (tid == 0) {
        float s = 0.f;
#pragma unroll
        for (int k = 0; k < 8; ++k) s += sr[k];
        g_D2[row] = s;
    }
}

// ===========================================================================
// K5: per (bn,i): rw softmax -> gw softmax
// ===========================================================================
__global__ void gw_kernel()
{
    int blk = blockIdx.x;
    int bn = blk / PDIM, i = blk % PDIM;
    int b = bn / NR, m = bn % NR;
    int tid = threadIdx.x;
    int w = tid >> 5, lane = tid & 31;
    __shared__ float sL[PDIM], sD[PDIM], sred[2];
    const float* vv = g_v + bn*RELC;
    const float* uu = g_u + bn*RELC;

    for (int j = w; j < PDIM; j += 4) {
        int R  = m*(PDIM*PDIM) + i*PDIM + j;
        int si = R / (NR*PDIM);
        size_t rowbase = ((size_t)b*PDIM*PDIM + (size_t)si*PDIM + j) * RELC;
        const float* rs = g_relS + rowbase;
        const float* rc = g_relC + rowbase;
        float s1 = 0.f, s2 = 0.f;
        for (int c = lane; c < RELC; c += 32) { s1 += rs[c]*vv[c]; s2 += rc[c]*uu[c]; }
#pragma unroll
        for (int off = 16; off; off >>= 1) {
            s1 += __shfl_xor_sync(0xffffffffu, s1, off);
            s2 += __shfl_xor_sync(0xffffffffu, s2, off);
        }
        if (lane == 0) { sL[j] = s1; sD[j] = s2; }
    }
    __syncthreads();
    if (tid == 0) { float mx = -1e30f; for (int j=0;j<PDIM;++j) mx = fmaxf(mx, sL[j]); sred[0] = mx; }
    __syncthreads();
    if (tid < PDIM) sL[tid] = __expf(sL[tid] - sred[0]);
    __syncthreads();
    if (tid == 0) { float s = 0.f; for (int j=0;j<PDIM;++j) s += sL[j]; sred[1] = 1.0f/s; }
    __syncthreads();
    if (tid < PDIM) sL[tid] = sL[tid]*sred[1]*sD[tid] + g_D2[bn*PDIM + tid];
    __syncthreads();
    if (tid == 0) { float mx = -1e30f; for (int j=0;j<PDIM;++j) mx = fmaxf(mx, sL[j]); sred[0] = mx; }
    __syncthreads();
    if (tid < PDIM) sL[tid] = __expf(sL[tid] - sred[0]);
    __syncthreads();
    if (tid == 0) { float s = 0.f; for (int j=0;j<PDIM;++j) s += sL[j]; sred[1] = 1.0f/s; }
    __syncthreads();
    if (tid < PDIM) g_gw[(size_t)blk*PDIM + tid] = sL[tid]*sred[1];
}

// ===========================================================================
// K6: img_ws + assemble cii (fp32) + bf16 split of cii
// ===========================================================================
__global__ void imgws_kernel(const float* __restrict__ img)
{
    int chunk = blockIdx.x, bn = blockIdx.y, tid = threadIdx.x;
    __shared__ float sg[PDIM*PDIM];
    for (int t = tid; t < PDIM*PDIM; t += 256) sg[t] = g_gw[(size_t)bn*PDIM*PDIM + t];
    __syncthreads();

    int f = chunk*256 + tid;
    float acc[PDIM];
#pragma unroll
    for (int i = 0; i < PDIM; ++i) acc[i] = 0.f;
    const float* ib = img + (size_t)bn*PDIM*IMGF + f;
#pragma unroll 4
    for (int j = 0; j < PDIM; ++j) {
        float vj = ib[(size_t)j*IMGF];
#pragma unroll
        for (int i = 0; i < PDIM; ++i) acc[i] += sg[i*PDIM + j] * vj;
    }
    size_t cb = (size_t)bn*PDIM*F2 + f;
#pragma unroll
    for (int i = 0; i < PDIM; ++i) {
        float iv = ib[(size_t)i*IMGF];
        size_t o0 = cb + (size_t)i*F2;
        size_t o1 = o0 + IMGF;
        g_cii[o0] = iv;
        g_cii[o1] = acc[i];
        __nv_bfloat16 h, l;
        split2(iv, h, l);     g_cAh[o0] = h; g_cAl[o0] = l;
        split2(acc[i], h, l); g_cAh[o1] = h; g_cAl[o1] = l;
    }
}

// ===========================================================================
// Launch
// ===========================================================================
extern "C" void kernel_launch(void* const* d_in, const int* in_sizes, int n_in,
                              void* d_out, int out_size)
{
    const float* relation = (const float*)d_in[0];
    const float* img      = (const float*)d_in[1];
    const float* ques     = (const float*)d_in[2];
    const float* Wcr      = (const float*)d_in[3];
    const float* bcr      = (const float*)d_in[4];
    const float* Wq       = (const float*)d_in[5];
    const float* bq       = (const float*)d_in[6];
    const float* Wrw      = (const float*)d_in[7];
    const float* Wc       = (const float*)d_in[9];
    const float* bc       = (const float*)d_in[10];
    const float* Wg       = (const float*)d_in[11];
    const float* Ww       = (const float*)d_in[13];
    const float* bw       = (const float*)d_in[14];
    const float* Wi       = (const float*)d_in[15];
    const float* bi       = (const float*)d_in[16];
    float* out = (float*)d_out;

    cudaFuncSetAttribute(hgemm<0>, cudaFuncAttributeMaxDynamicSharedMemorySize, HG_SMEM);
    cudaFuncSetAttribute(hgemm<1>, cudaFuncAttributeMaxDynamicSharedMemorySize, HG_SMEM);
    cudaFuncSetAttribute(hgemm<2>, cudaFuncAttributeMaxDynamicSharedMemorySize, HG_SMEM);
    cudaFuncSetAttribute(hgemm_dual, cudaFuncAttributeMaxDynamicSharedMemorySize, HG_SMEM);

    float *p_relC, *p_imgC, *p_cii;
    __nv_bfloat16 *p_rSh,*p_rSl,*p_iAh,*p_iAl,*p_cAh,*p_cAl,*p_gAh,*p_gAl;
    __nv_bfloat16 *p_B1h,*p_B1l,*p_B2h,*p_B2l,*p_Bwh,*p_Bwl,*p_Bih,*p_Bil;
    cudaGetSymbolAddress((void**)&p_relC, g_relC);
    cudaGetSymbolAddress((void**)&p_imgC, g_imgC);
    cudaGetSymbolAddress((void**)&p_cii,  g_cii);
    cudaGetSymbolAddress((void**)&p_rSh, g_rSh); cudaGetSymbolAddress((void**)&p_rSl, g_rSl);
    cudaGetSymbolAddress((void**)&p_iAh, g_iAh); cudaGetSymbolAddress((void**)&p_iAl, g_iAl);
    cudaGetSymbolAddress((void**)&p_cAh, g_cAh); cudaGetSymbolAddress((void**)&p_cAl, g_cAl);
    cudaGetSymbolAddress((void**)&p_gAh, g_gAh); cudaGetSymbolAddress((void**)&p_gAl, g_gAl);
    cudaGetSymbolAddress((void**)&p_B1h, g_B1h); cudaGetSymbolAddress((void**)&p_B1l, g_B1l);
    cudaGetSymbolAddress((void**)&p_B2h, g_B2h); cudaGetSymbolAddress((void**)&p_B2l, g_B2l);
    cudaGetSymbolAddress((void**)&p_Bwh, g_Bwh); cudaGetSymbolAddress((void**)&p_Bwl, g_Bwl);
    cudaGetSymbolAddress((void**)&p_Bih, g_Bih); cudaGetSymbolAddress((void**)&p_Bil, g_Bil);

    // 1. relS (fp32 + split)
    rels_kernel<<<RELROWS, RELC>>>(relation, Wcr, bcr);
    // 2. question vectors
    ques_kernel<<<BN, RELC>>>(ques, Wq, bq, Wrw, Wg);
    // 3. all operand conversions (merged)
    convert_all<<<2048 + 64 + 512 + 16384 + 8192, 256>>>(img, Wc, Ww, Wi);
    // 4. imgC GEMM + relC GEMM merged (106 CTAs, one wave)  <-- profiled slot
    hgemm_dual<<<106, 256, HG_SMEM>>>(p_iAh, p_iAl, p_B2h, p_B2l, bc, p_imgC,
                                      p_rSh, p_rSl, p_B1h, p_B1l, p_relC);
    // 5. D2
    d2_kernel<<<ROWS, RELC>>>();
    // 6. attention weights
    gw_kernel<<<ROWS, 128>>>();
    // 7. img_ws + cii (+ split)
    imgws_kernel<<<dim3(IMGF/256, BN), 256>>>(img);
    // 8. gated = sigmoid(cii@Ww + bw)*cii -> bf16 split   (M=1440, N=4096, K=4096)
    hgemm<2><<<dim3(F2/128, (ROWS+127)/128), 256, HG_SMEM>>>(
        ROWS, F2, F2, p_cAh, p_cAl, p_Bwh, p_Bwl, bw, p_cii, nullptr, p_gAh, p_gAl);
    // 9. out = gated @ Wi + bi  (M=1440, N=2048, K=4096)
    hgemm<1><<<dim3(IMGF/128, (ROWS+127)/128), 256, HG_SMEM>>>(
        ROWS, IMGF, F2, p_gAh, p_gAl, p_Bih, p_Bil, bi, nullptr, out, nullptr, nullptr);
}

// round 9
// speedup vs baseline: 2.8393x; 1.1238x over previous
#include <cuda_runtime.h>
#include <cuda_bf16.h>
#include <cstdint>
#include <cstddef>

// Problem constants
#define PDIM 36
#define BB 4
#define NR 10
#define BN 40
#define RELD 7
#define RELC 256
#define LSTM 512
#define IMGF 2048
#define ROWS (BN*PDIM)          // 1440
#define RELROWS (BB*PDIM*PDIM)  // 5184
#define F2 (2*IMGF)             // 4096

// ===========================================================================
// Helpers
// ===========================================================================
__device__ __forceinline__ uint32_t smem_u32(const void* p) {
    uint32_t a;
    asm("{ .reg .u64 t; cvta.to.shared.u64 t, %1; cvt.u32.u64 %0, t; }" : "=r"(a) : "l"(p));
    return a;
}
__device__ __forceinline__ float sigmoidf_(float x) { return 1.0f / (1.0f + __expf(-x)); }
__device__ __forceinline__ void split2(float x, __nv_bfloat16& h, __nv_bfloat16& l) {
    h = __float2bfloat16(x);
    l = __float2bfloat16(x - __bfloat162float(h));
}
#define SWZ128(off) ((off) ^ (((off) >> 3) & 0x70))

__device__ __forceinline__ void cp_async16(uint32_t dst, const void* src, int szbytes) {
    asm volatile("cp.async.cg.shared.global [%0], [%1], 16, %2;"
                 :: "r"(dst), "l"(src), "r"(szbytes) : "memory");
}
#define CP_COMMIT() asm volatile("cp.async.commit_group;" ::: "memory")
#define CP_WAIT1()  asm volatile("cp.async.wait_group 1;" ::: "memory")
#define CP_WAIT0()  asm volatile("cp.async.wait_group 0;" ::: "memory")

__device__ __forceinline__ void ldm4(uint32_t* r, uint32_t a) {
    asm volatile("ldmatrix.sync.aligned.m8n8.x4.shared.b16 {%0,%1,%2,%3}, [%4];"
                 : "=r"(r[0]), "=r"(r[1]), "=r"(r[2]), "=r"(r[3]) : "r"(a));
}
__device__ __forceinline__ void mma16816(float* c, const uint32_t* a, uint32_t b0, uint32_t b1) {
    asm volatile("mma.sync.aligned.m16n8k16.row.col.f32.bf16.bf16.f32 "
                 "{%0,%1,%2,%3}, {%4,%5,%6,%7}, {%8,%9}, {%0,%1,%2,%3};"
                 : "+f"(c[0]), "+f"(c[1]), "+f"(c[2]), "+f"(c[3])
                 : "r"(a[0]), "r"(a[1]), "r"(a[2]), "r"(a[3]), "r"(b0), "r"(b1));
}

// ===========================================================================
// Scratch (device globals; no allocations allowed)
// ===========================================================================
__device__ float g_relS [RELROWS*RELC];
__device__ float g_relC [RELROWS*RELC];
__device__ float g_v    [BN*RELC];
__device__ float g_u    [BN*RELC];
__device__ float g_imgC [ROWS*RELC];
__device__ float g_D2   [ROWS];
__device__ float g_gw   [ROWS*PDIM];
__device__ float g_cii  [ROWS*F2];
// bf16 hi/lo operand splits
__device__ __nv_bfloat16 g_rSh[RELROWS*RELC], g_rSl[RELROWS*RELC];
__device__ __nv_bfloat16 g_iAh[ROWS*IMGF],    g_iAl[ROWS*IMGF];
__device__ __nv_bfloat16 g_cAh[(size_t)ROWS*F2], g_cAl[(size_t)ROWS*F2];
__device__ __nv_bfloat16 g_gAh[(size_t)ROWS*F2], g_gAl[(size_t)ROWS*F2];
__device__ __nv_bfloat16 g_B1h[RELC*RELC],    g_B1l[RELC*RELC];
__device__ __nv_bfloat16 g_B2h[RELC*IMGF],    g_B2l[RELC*IMGF];
__device__ __nv_bfloat16 g_Bwh[(size_t)F2*F2],   g_Bwl[(size_t)F2*F2];
__device__ __nv_bfloat16 g_Bih[(size_t)IMGF*F2], g_Bil[(size_t)IMGF*F2];

// ===========================================================================
// K1: relS = sigmoid(relation @ Wcr + bcr) + bf16 split
// ===========================================================================
__global__ void rels_kernel(const float* __restrict__ relation,
                            const float* __restrict__ Wcr,
                            const float* __restrict__ bcr)
{
    int r = blockIdx.x, c = threadIdx.x;
    __shared__ float rd[RELD];
    if (c < RELD) rd[c] = relation[r*RELD + c];
    __syncthreads();
    float acc = bcr[c];
#pragma unroll
    for (int d = 0; d < RELD; ++d) acc += rd[d] * Wcr[d*RELC + c];
    float s = sigmoidf_(acc);
    size_t idx = (size_t)r*RELC + c;
    g_relS[idx] = s;
    __nv_bfloat16 h, l; split2(s, h, l);
    g_rSh[idx] = h; g_rSl[idx] = l;
}

// ===========================================================================
// K2: question vectors
// ===========================================================================
__global__ void ques_kernel(const float* __restrict__ ques,
                            const float* __restrict__ Wq,
                            const float* __restrict__ bq,
                            const float* __restrict__ Wrw,
                            const float* __restrict__ Wg)
{
    int bn = blockIdx.x, c = threadIdx.x;
    __shared__ float q[LSTM];
    q[c] = ques[bn*LSTM + c];
    q[c + 256] = ques[bn*LSTM + c + 256];
    __syncthreads();
    float acc = bq[c];
    for (int k = 0; k < LSTM; ++k) acc += q[k] * Wq[k*RELC + c];
    float s = sigmoidf_(acc);
    g_v[bn*RELC + c] = s * Wrw[c];
    g_u[bn*RELC + c] = s * Wg[c];
}

// ===========================================================================
// K3 (merged): img bf16 split + all 4 weight transpose-splits
// ===========================================================================
__global__ void convert_all(const float* __restrict__ img,
                            const float* __restrict__ Wc,
                            const float* __restrict__ Ww,
                            const float* __restrict__ Wi)
{
    int b = blockIdx.x;
    if (b < 2048) {
        size_t n = (size_t)ROWS*IMGF;
        for (size_t i = (size_t)b*256 + threadIdx.x; i < n; i += (size_t)2048*256) {
            __nv_bfloat16 h, l; split2(img[i], h, l);
            g_iAh[i] = h; g_iAl[i] = l;
        }
        return;
    }
    b -= 2048;
    const float* W; int K, N; __nv_bfloat16 *Bh, *Bl; int bx, by;
    if (b < 64)             { W = Wc;             K = RELC; N = RELC; Bh = g_B1h; Bl = g_B1l; bx = b % 8;   by = b / 8; }
    else if (b < 576)       { b -= 64;  W = Wc + RELC*RELC; K = IMGF; N = RELC; Bh = g_B2h; Bl = g_B2l; bx = b % 8;   by = b / 8; }
    else if (b < 576+16384) { b -= 576; W = Ww;   K = F2;   N = F2;   Bh = g_Bwh; Bl = g_Bwl; bx = b % 128; by = b / 128; }
    else                    { b -= 16960; W = Wi; K = F2;   N = IMGF; Bh = g_Bih; Bl = g_Bil; bx = b % 64;  by = b / 64; }

    __shared__ float tile[32][33];
    int tx = threadIdx.x & 31, ty = threadIdx.x >> 5;
    int n0 = bx * 32, k0 = by * 32;
#pragma unroll
    for (int r = 0; r < 4; ++r)
        tile[ty + r*8][tx] = W[(size_t)(k0 + ty + r*8) * N + n0 + tx];
    __syncthreads();
#pragma unroll
    for (int r = 0; r < 4; ++r) {
        int n = n0 + ty + r*8, k = k0 + tx;
        float v = tile[tx][ty + r*8];
        __nv_bfloat16 h, l; split2(v, h, l);
        Bh[(size_t)n*K + k] = h;
        Bl[(size_t)n*K + k] = l;
    }
}

// ===========================================================================
// bf16-split GEMM tile body. CTA tile 128x128, BK=64, 16 warps 4x4 grid
// (warp tile 32x32, 4 warps/SMSP for latency hiding), 3-stage cp.async
// pipeline. 3 terms term-major: AhBh + AhBl + AlBh.
// EPI: 0 plain fp32, 1 +bias fp32, 2 sigmoid(acc+bias)*aux -> bf16 hi/lo
// ===========================================================================
#define STAGE_B 65536
#define NSTAGE 3
#define HG_SMEM (NSTAGE*STAGE_B)
#define GTHREADS 512

struct Frags {
    uint32_t ah[2][4];
    uint32_t al[2][4];
    uint32_t bh[2][4];
    uint32_t bl[2][4];
};

template<int EPI>
__device__ __forceinline__ void gemm_tile(
    int M, int N, int K, int m0, int n0,
    const __nv_bfloat16* __restrict__ Ah, const __nv_bfloat16* __restrict__ Al,
    const __nv_bfloat16* __restrict__ Bh, const __nv_bfloat16* __restrict__ Bl,
    const float* __restrict__ bias, const float* __restrict__ aux,
    float* __restrict__ C,
    __nv_bfloat16* __restrict__ Ch, __nv_bfloat16* __restrict__ Cl,
    uint32_t sbase)
{
    const int tid = threadIdx.x;
    const int lid = tid & 31;
    const int wid = tid >> 5;       // 0..15
    const int wm = wid & 3;         // M strip (32 rows)
    const int wn = wid >> 2;        // N strip (32 cols)

    float acc[2][4][4];
#pragma unroll
    for (int i = 0; i < 2; ++i)
#pragma unroll
        for (int j = 0; j < 4; ++j)
#pragma unroll
            for (int e = 0; e < 4; ++e) acc[i][j][e] = 0.f;

    // loader mapping: 4 threads per 128B row, 2 x 16B segments each
    const int lrow = tid >> 2;           // 0..127
    const int lseg = (tid & 3) * 2;      // 0,2,4,6
    const int gmrow = m0 + lrow;
    const int a_ok = (gmrow < M) ? 16 : 0;
    const size_t aoff = (size_t)(a_ok ? gmrow : 0) * K;
    const size_t boff = (size_t)(n0 + lrow) * K;

    const int nch = K >> 6;

    auto load_stage = [&](int c, int buf) {
        const int k0 = c << 6;
        const uint32_t sb = sbase + buf * STAGE_B;
        const char* pAh = (const char*)(Ah + aoff + k0);
        const char* pAl = (const char*)(Al + aoff + k0);
        const char* pBh = (const char*)(Bh + boff + k0);
        const char* pBl = (const char*)(Bl + boff + k0);
#pragma unroll
        for (int s = 0; s < 2; ++s) {
            const int colb = (lseg + s) * 16;
            const uint32_t sw = SWZ128((uint32_t)(lrow * 128 + colb));
            cp_async16(sb + sw,         pAh + colb, a_ok);
            cp_async16(sb + 16384 + sw, pAl + colb, a_ok);
            cp_async16(sb + 32768 + sw, pBh + colb, 16);
            cp_async16(sb + 49152 + sw, pBl + colb, 16);
        }
        CP_COMMIT();
    };

    // fragment lane components
    const int matA  = lid >> 3;
    const int rowA  = (lid & 7) + ((matA & 1) << 3);
    const int kselA = (matA >> 1) << 4;
    const int rowB  = (lid & 7) + ((matA >> 1) << 3);
    const int kselB = (matA & 1) << 4;

    auto load_frags = [&](uint32_t sb, int ks, Frags& F) {
        const int kb = ks << 5;
#pragma unroll
        for (int mi = 0; mi < 2; ++mi) {
            uint32_t off = SWZ128((uint32_t)((wm*32 + mi*16 + rowA) * 128 + kb + kselA));
            ldm4(F.ah[mi], sb + off);
            ldm4(F.al[mi], sb + 16384u + off);
        }
#pragma unroll
        for (int nb = 0; nb < 2; ++nb) {
            uint32_t off = SWZ128((uint32_t)((wn*32 + nb*16 + rowB) * 128 + kb + kselB));
            ldm4(F.bh[nb], sb + 32768u + off);
            ldm4(F.bl[nb], sb + 49152u + off);
        }
    };

    auto mma_all = [&](Frags& F) {
        // term-major: consecutive MMAs hit distinct accumulators
#pragma unroll
        for (int mi = 0; mi < 2; ++mi)
#pragma unroll
            for (int ni = 0; ni < 4; ++ni)
                mma16816(acc[mi][ni], F.ah[mi],
                         F.bh[ni >> 1][(ni & 1) * 2], F.bh[ni >> 1][(ni & 1) * 2 + 1]);
#pragma unroll
        for (int mi = 0; mi < 2; ++mi)
#pragma unroll
            for (int ni = 0; ni < 4; ++ni)
                mma16816(acc[mi][ni], F.ah[mi],
                         F.bl[ni >> 1][(ni & 1) * 2], F.bl[ni >> 1][(ni & 1) * 2 + 1]);
#pragma unroll
        for (int mi = 0; mi < 2; ++mi)
#pragma unroll
            for (int ni = 0; ni < 4; ++ni)
                mma16816(acc[mi][ni], F.al[mi],
                         F.bh[ni >> 1][(ni & 1) * 2], F.bh[ni >> 1][(ni & 1) * 2 + 1]);
    };

    load_stage(0, 0);
    if (nch > 1) load_stage(1, 1);
    for (int c = 0; c < nch; ++c) {
        if (c + 1 < nch) { CP_WAIT1(); } else { CP_WAIT0(); }
        __syncthreads();
        if (c + 2 < nch) load_stage(c + 2, (c + 2) % NSTAGE);
        const uint32_t sb = sbase + (c % NSTAGE) * STAGE_B;
#pragma unroll
        for (int ks = 0; ks < 4; ++ks) {
            Frags f;
            load_frags(sb, ks, f);
            mma_all(f);
        }
    }

    // epilogue: lane l -> rows (l>>2)+{0,8}, cols (l&3)*2+{0,1}
    const int er = lid >> 2;
    const int ec = (lid & 3) * 2;
#pragma unroll
    for (int mi = 0; mi < 2; ++mi) {
#pragma unroll
        for (int half = 0; half < 2; ++half) {
            const int gm = m0 + wm*32 + mi*16 + er + half*8;
            if (gm >= M) continue;
#pragma unroll
            for (int ni = 0; ni < 4; ++ni) {
                const int gn = n0 + wn*32 + ni*8 + ec;
                float v0 = acc[mi][ni][half*2 + 0];
                float v1 = acc[mi][ni][half*2 + 1];
                if (EPI == 0) {
                    float2 r; r.x = v0; r.y = v1;
                    *reinterpret_cast<float2*>(C + (size_t)gm*N + gn) = r;
                } else if (EPI == 1) {
                    float2 r; r.x = v0 + bias[gn]; r.y = v1 + bias[gn + 1];
                    *reinterpret_cast<float2*>(C + (size_t)gm*N + gn) = r;
                } else {
                    const size_t o = (size_t)gm*N + gn;
                    float g0 = sigmoidf_(v0 + bias[gn])     * aux[o];
                    float g1 = sigmoidf_(v1 + bias[gn + 1]) * aux[o + 1];
                    __nv_bfloat16 h0, l0, h1, l1;
                    split2(g0, h0, l0); split2(g1, h1, l1);
                    __nv_bfloat162 ph; ph.x = h0; ph.y = h1;
                    __nv_bfloat162 pl; pl.x = l0; pl.y = l1;
                    *reinterpret_cast<__nv_bfloat162*>(Ch + o) = ph;
                    *reinterpret_cast<__nv_bfloat162*>(Cl + o) = pl;
                }
            }
        }
    }
}

template<int EPI>
__global__ __launch_bounds__(GTHREADS, 1)
void hgemm(int M, int N, int K,
           const __nv_bfloat16* __restrict__ Ah, const __nv_bfloat16* __restrict__ Al,
           const __nv_bfloat16* __restrict__ Bh, const __nv_bfloat16* __restrict__ Bl,
           const float* __restrict__ bias, const float* __restrict__ aux,
           float* __restrict__ C,
           __nv_bfloat16* __restrict__ Ch, __nv_bfloat16* __restrict__ Cl)
{
    extern __shared__ char sm[];
    gemm_tile<EPI>(M, N, K, blockIdx.y * 128, blockIdx.x * 128,
                   Ah, Al, Bh, Bl, bias, aux, C, Ch, Cl, smem_u32(sm));
}

// Merged launch: blocks [0,24) imgC GEMM (EPI1), [24,106) relC GEMM (EPI0)
__global__ __launch_bounds__(GTHREADS, 1)
void hgemm_dual(const __nv_bfloat16* __restrict__ iAh, const __nv_bfloat16* __restrict__ iAl,
                const __nv_bfloat16* __restrict__ B2h, const __nv_bfloat16* __restrict__ B2l,
                const float* __restrict__ bc, float* __restrict__ imgC,
                const __nv_bfloat16* __restrict__ rSh, const __nv_bfloat16* __restrict__ rSl,
                const __nv_bfloat16* __restrict__ B1h, const __nv_bfloat16* __restrict__ B1l,
                float* __restrict__ relC)
{
    extern __shared__ char sm[];
    const uint32_t sbase = smem_u32(sm);
    int blk = blockIdx.x;
    if (blk < 24) {
        gemm_tile<1>(ROWS, RELC, IMGF, (blk >> 1) * 128, (blk & 1) * 128,
                     iAh, iAl, B2h, B2l, bc, nullptr, imgC, nullptr, nullptr, sbase);
    } else {
        int idx = blk - 24;
        gemm_tile<0>(RELROWS, RELC, RELC, (idx >> 1) * 128, (idx & 1) * 128,
                     rSh, rSl, B1h, B1l, nullptr, nullptr, relC, nullptr, nullptr, sbase);
    }
}

// ===========================================================================
// K4: D2[bn,j] = imgC[bn,j,:] . u[bn,:]
// ===========================================================================
__global__ void d2_kernel()
{
    int row = blockIdx.x, bn = row / PDIM, tid = threadIdx.x;
    float p = g_imgC[(size_t)row*RELC + tid] * g_u[bn*RELC + tid];
    __shared__ float sr[8];
#pragma unroll
    for (int off = 16; off; off >>= 1) p += __shfl_xor_sync(0xffffffffu, p, off);
    if ((tid & 31) == 0) sr[tid >> 5] = p;
    __syncthreads();
    if (tid == 0) {
        float s = 0.f;
#pragma unroll
        for (int k = 0; k < 8; ++k) s += sr[k];
        g_D2[row] = s;
    }
}

// ===========================================================================
// K5: per (bn,i): rw softmax -> gw softmax
// ===========================================================================
__global__ void gw_kernel()
{
    int blk = blockIdx.x;
    int bn = blk / PDIM, i = blk % PDIM;
    int b = bn / NR, m = bn % NR;
    int tid = threadIdx.x;
    int w = tid >> 5, lane = tid & 31;
    __shared__ float sL[PDIM], sD[PDIM], sred[2];
    const float* vv = g_v + bn*RELC;
    const float* uu = g_u + bn*RELC;

    for (int j = w; j < PDIM; j += 4) {
        int R  = m*(PDIM*PDIM) + i*PDIM + j;
        int si = R / (NR*PDIM);
        size_t rowbase = ((size_t)b*PDIM*PDIM + (size_t)si*PDIM + j) * RELC;
        const float* rs = g_relS + rowbase;
        const float* rc = g_relC + rowbase;
        float s1 = 0.f, s2 = 0.f;
        for (int c = lane; c < RELC; c += 32) { s1 += rs[c]*vv[c]; s2 += rc[c]*uu[c]; }
#pragma unroll
        for (int off = 16; off; off >>= 1) {
            s1 += __shfl_xor_sync(0xffffffffu, s1, off);
            s2 += __shfl_xor_sync(0xffffffffu, s2, off);
        }
        if (lane == 0) { sL[j] = s1; sD[j] = s2; }
    }
    __syncthreads();
    if (tid == 0) { float mx = -1e30f; for (int j=0;j<PDIM;++j) mx = fmaxf(mx, sL[j]); sred[0] = mx; }
    __syncthreads();
    if (tid < PDIM) sL[tid] = __expf(sL[tid] - sred[0]);
    __syncthreads();
    if (tid == 0) { float s = 0.f; for (int j=0;j<PDIM;++j) s += sL[j]; sred[1] = 1.0f/s; }
    __syncthreads();
    if (tid < PDIM) sL[tid] = sL[tid]*sred[1]*sD[tid] + g_D2[bn*PDIM + tid];
    __syncthreads();
    if (tid == 0) { float mx = -1e30f; for (int j=0;j<PDIM;++j) mx = fmaxf(mx, sL[j]); sred[0] = mx; }
    __syncthreads();
    if (tid < PDIM) sL[tid] = __expf(sL[tid] - sred[0]);
    __syncthreads();
    if (tid == 0) { float s = 0.f; for (int j=0;j<PDIM;++j) s += sL[j]; sred[1] = 1.0f/s; }
    __syncthreads();
    if (tid < PDIM) g_gw[(size_t)blk*PDIM + tid] = sL[tid]*sred[1];
}

// ===========================================================================
// K6: img_ws + assemble cii (fp32) + bf16 split of cii
// ===========================================================================
__global__ void imgws_kernel(const float* __restrict__ img)
{
    int chunk = blockIdx.x, bn = blockIdx.y, tid = threadIdx.x;
    __shared__ float sg[PDIM*PDIM];
    for (int t = tid; t < PDIM*PDIM; t += 256) sg[t] = g_gw[(size_t)bn*PDIM*PDIM + t];
    __syncthreads();

    int f = chunk*256 + tid;
    float acc[PDIM];
#pragma unroll
    for (int i = 0; i < PDIM; ++i) acc[i] = 0.f;
    const float* ib = img + (size_t)bn*PDIM*IMGF + f;
#pragma unroll 4
    for (int j = 0; j < PDIM; ++j) {
        float vj = ib[(size_t)j*IMGF];
#pragma unroll
        for (int i = 0; i < PDIM; ++i) acc[i] += sg[i*PDIM + j] * vj;
    }
    size_t cb = (size_t)bn*PDIM*F2 + f;
#pragma unroll
    for (int i = 0; i < PDIM; ++i) {
        float iv = ib[(size_t)i*IMGF];
        size_t o0 = cb + (size_t)i*F2;
        size_t o1 = o0 + IMGF;
        g_cii[o0] = iv;
        g_cii[o1] = acc[i];
        __nv_bfloat16 h, l;
        split2(iv, h, l);     g_cAh[o0] = h; g_cAl[o0] = l;
        split2(acc[i], h, l); g_cAh[o1] = h; g_cAl[o1] = l;
    }
}

// ===========================================================================
// Launch
// ===========================================================================
extern "C" void kernel_launch(void* const* d_in, const int* in_sizes, int n_in,
                              void* d_out, int out_size)
{
    const float* relation = (const float*)d_in[0];
    const float* img      = (const float*)d_in[1];
    const float* ques     = (const float*)d_in[2];
    const float* Wcr      = (const float*)d_in[3];
    const float* bcr      = (const float*)d_in[4];
    const float* Wq       = (const float*)d_in[5];
    const float* bq       = (const float*)d_in[6];
    const float* Wrw      = (const float*)d_in[7];
    const float* Wc       = (const float*)d_in[9];
    const float* bc       = (const float*)d_in[10];
    const float* Wg       = (const float*)d_in[11];
    const float* Ww       = (const float*)d_in[13];
    const float* bw       = (const float*)d_in[14];
    const float* Wi       = (const float*)d_in[15];
    const float* bi       = (const float*)d_in[16];
    float* out = (float*)d_out;

    cudaFuncSetAttribute(hgemm<0>, cudaFuncAttributeMaxDynamicSharedMemorySize, HG_SMEM);
    cudaFuncSetAttribute(hgemm<1>, cudaFuncAttributeMaxDynamicSharedMemorySize, HG_SMEM);
    cudaFuncSetAttribute(hgemm<2>, cudaFuncAttributeMaxDynamicSharedMemorySize, HG_SMEM);
    cudaFuncSetAttribute(hgemm_dual, cudaFuncAttributeMaxDynamicSharedMemorySize, HG_SMEM);

    float *p_relC, *p_imgC, *p_cii;
    __nv_bfloat16 *p_rSh,*p_rSl,*p_iAh,*p_iAl,*p_cAh,*p_cAl,*p_gAh,*p_gAl;
    __nv_bfloat16 *p_B1h,*p_B1l,*p_B2h,*p_B2l,*p_Bwh,*p_Bwl,*p_Bih,*p_Bil;
    cudaGetSymbolAddress((void**)&p_relC, g_relC);
    cudaGetSymbolAddress((void**)&p_imgC, g_imgC);
    cudaGetSymbolAddress((void**)&p_cii,  g_cii);
    cudaGetSymbolAddress((void**)&p_rSh, g_rSh); cudaGetSymbolAddress((void**)&p_rSl, g_rSl);
    cudaGetSymbolAddress((void**)&p_iAh, g_iAh); cudaGetSymbolAddress((void**)&p_iAl, g_iAl);
    cudaGetSymbolAddress((void**)&p_cAh, g_cAh); cudaGetSymbolAddress((void**)&p_cAl, g_cAl);
    cudaGetSymbolAddress((void**)&p_gAh, g_gAh); cudaGetSymbolAddress((void**)&p_gAl, g_gAl);
    cudaGetSymbolAddress((void**)&p_B1h, g_B1h); cudaGetSymbolAddress((void**)&p_B1l, g_B1l);
    cudaGetSymbolAddress((void**)&p_B2h, g_B2h); cudaGetSymbolAddress((void**)&p_B2l, g_B2l);
    cudaGetSymbolAddress((void**)&p_Bwh, g_Bwh); cudaGetSymbolAddress((void**)&p_Bwl, g_Bwl);
    cudaGetSymbolAddress((void**)&p_Bih, g_Bih); cudaGetSymbolAddress((void**)&p_Bil, g_Bil);

    // 1. relS (fp32 + split)
    rels_kernel<<<RELROWS, RELC>>>(relation, Wcr, bcr);
    // 2. question vectors
    ques_kernel<<<BN, RELC>>>(ques, Wq, bq, Wrw, Wg);
    // 3. all operand conversions (merged)
    convert_all<<<2048 + 64 + 512 + 16384 + 8192, 256>>>(img, Wc, Ww, Wi);
    // 4. imgC GEMM + relC GEMM merged (106 CTAs, one wave)  <-- profiled slot
    hgemm_dual<<<106, GTHREADS, HG_SMEM>>>(p_iAh, p_iAl, p_B2h, p_B2l, bc, p_imgC,
                                           p_rSh, p_rSl, p_B1h, p_B1l, p_relC);
    // 5. D2
    d2_kernel<<<ROWS, RELC>>>();
    // 6. attention weights
    gw_kernel<<<ROWS, 128>>>();
    // 7. img_ws + cii (+ split)
    imgws_kernel<<<dim3(IMGF/256, BN), 256>>>(img);
    // 8. gated = sigmoid(cii@Ww + bw)*cii -> bf16 split   (M=1440, N=4096, K=4096)
    hgemm<2><<<dim3(F2/128, (ROWS+127)/128), GTHREADS, HG_SMEM>>>(
        ROWS, F2, F2, p_cAh, p_cAl, p_Bwh, p_Bwl, bw, p_cii, nullptr, p_gAh, p_gAl);
    // 9. out = gated @ Wi + bi  (M=1440, N=2048, K=4096)
    hgemm<1><<<dim3(IMGF/128, (ROWS+127)/128), GTHREADS, HG_SMEM>>>(
        ROWS, IMGF, F2, p_gAh, p_gAl, p_Bih, p_Bil, bi, nullptr, out, nullptr, nullptr);
}

// round 15
// speedup vs baseline: 3.3464x; 1.1786x over previous
#include <cuda_runtime.h>
#include <cuda_bf16.h>
#include <cstdint>
#include <cstddef>

// Problem constants
#define PDIM 36
#define BB 4
#define NR 10
#define BN 40
#define RELD 7
#define RELC 256
#define LSTM 512
#define IMGF 2048
#define ROWS (BN*PDIM)          // 1440
#define RELROWS (BB*PDIM*PDIM)  // 5184
#define F2 (2*IMGF)             // 4096

// ===========================================================================
// Helpers
// ===========================================================================
__device__ __forceinline__ uint32_t smem_u32(const void* p) {
    uint32_t a;
    asm("{ .reg .u64 t; cvta.to.shared.u64 t, %1; cvt.u32.u64 %0, t; }" : "=r"(a) : "l"(p));
    return a;
}
__device__ __forceinline__ float sigmoidf_(float x) { return 1.0f / (1.0f + __expf(-x)); }
__device__ __forceinline__ void split2(float x, __nv_bfloat16& h, __nv_bfloat16& l) {
    h = __float2bfloat16(x);
    l = __float2bfloat16(x - __bfloat162float(h));
}
#define SWZ128(off) ((off) ^ (((off) >> 3) & 0x70))

__device__ __forceinline__ void cp_async16(uint32_t dst, const void* src, int szbytes) {
    asm volatile("cp.async.cg.shared.global [%0], [%1], 16, %2;"
                 :: "r"(dst), "l"(src), "r"(szbytes) : "memory");
}
#define CP_COMMIT() asm volatile("cp.async.commit_group;" ::: "memory")
#define CP_WAIT1()  asm volatile("cp.async.wait_group 1;" ::: "memory")
#define CP_WAIT0()  asm volatile("cp.async.wait_group 0;" ::: "memory")

__device__ __forceinline__ void ldm4(uint32_t* r, uint32_t a) {
    asm volatile("ldmatrix.sync.aligned.m8n8.x4.shared.b16 {%0,%1,%2,%3}, [%4];"
                 : "=r"(r[0]), "=r"(r[1]), "=r"(r[2]), "=r"(r[3]) : "r"(a));
}
__device__ __forceinline__ void mma16816(float* c, const uint32_t* a, uint32_t b0, uint32_t b1) {
    asm volatile("mma.sync.aligned.m16n8k16.row.col.f32.bf16.bf16.f32 "
                 "{%0,%1,%2,%3}, {%4,%5,%6,%7}, {%8,%9}, {%0,%1,%2,%3};"
                 : "+f"(c[0]), "+f"(c[1]), "+f"(c[2]), "+f"(c[3])
                 : "r"(a[0]), "r"(a[1]), "r"(a[2]), "r"(a[3]), "r"(b0), "r"(b1));
}

// ===========================================================================
// Scratch (device globals; no allocations allowed)
// ===========================================================================
__device__ float g_relS [RELROWS*RELC];
__device__ float g_relC [RELROWS*RELC];
__device__ float g_v    [BN*RELC];
__device__ float g_u    [BN*RELC];
__device__ float g_imgC [ROWS*RELC];
__device__ float g_D2   [ROWS];
__device__ float g_gw   [ROWS*PDIM];
__device__ float g_cii  [ROWS*F2];
// split-K partial accumulators
__device__ float g_pimg [4*ROWS*RELC];                 // imgC split-K4 partials
__device__ float g_pout [2*(size_t)ROWS*IMGF];        // out split-K2 partials
// bf16 hi/lo operand splits
__device__ __nv_bfloat16 g_rSh[RELROWS*RELC], g_rSl[RELROWS*RELC];
__device__ __nv_bfloat16 g_iAh[ROWS*IMGF],    g_iAl[ROWS*IMGF];
__device__ __nv_bfloat16 g_cAh[(size_t)ROWS*F2], g_cAl[(size_t)ROWS*F2];
__device__ __nv_bfloat16 g_gAh[(size_t)ROWS*F2], g_gAl[(size_t)ROWS*F2];
__device__ __nv_bfloat16 g_B1h[RELC*RELC],    g_B1l[RELC*RELC];
__device__ __nv_bfloat16 g_B2h[RELC*IMGF],    g_B2l[RELC*IMGF];
__device__ __nv_bfloat16 g_Bwh[(size_t)F2*F2],   g_Bwl[(size_t)F2*F2];
__device__ __nv_bfloat16 g_Bih[(size_t)IMGF*F2], g_Bil[(size_t)IMGF*F2];

// ===========================================================================
// K1: relS = sigmoid(relation @ Wcr + bcr) + bf16 split
// ===========================================================================
__global__ void rels_kernel(const float* __restrict__ relation,
                            const float* __restrict__ Wcr,
                            const float* __restrict__ bcr)
{
    int r = blockIdx.x, c = threadIdx.x;
    __shared__ float rd[RELD];
    if (c < RELD) rd[c] = relation[r*RELD + c];
    __syncthreads();
    float acc = bcr[c];
#pragma unroll
    for (int d = 0; d < RELD; ++d) acc += rd[d] * Wcr[d*RELC + c];
    float s = sigmoidf_(acc);
    size_t idx = (size_t)r*RELC + c;
    g_relS[idx] = s;
    __nv_bfloat16 h, l; split2(s, h, l);
    g_rSh[idx] = h; g_rSl[idx] = l;
}

// ===========================================================================
// K2: question vectors
// ===========================================================================
__global__ void ques_kernel(const float* __restrict__ ques,
                            const float* __restrict__ Wq,
                            const float* __restrict__ bq,
                            const float* __restrict__ Wrw,
                            const float* __restrict__ Wg)
{
    int bn = blockIdx.x, c = threadIdx.x;
    __shared__ float q[LSTM];
    q[c] = ques[bn*LSTM + c];
    q[c + 256] = ques[bn*LSTM + c + 256];
    __syncthreads();
    float acc = bq[c];
    for (int k = 0; k < LSTM; ++k) acc += q[k] * Wq[k*RELC + c];
    float s = sigmoidf_(acc);
    g_v[bn*RELC + c] = s * Wrw[c];
    g_u[bn*RELC + c] = s * Wg[c];
}

// ===========================================================================
// K3 (merged): img bf16 split + all 4 weight transpose-splits
// ===========================================================================
__global__ void convert_all(const float* __restrict__ img,
                            const float* __restrict__ Wc,
                            const float* __restrict__ Ww,
                            const float* __restrict__ Wi)
{
    int b = blockIdx.x;
    if (b < 2048) {
        size_t n = (size_t)ROWS*IMGF;
        for (size_t i = (size_t)b*256 + threadIdx.x; i < n; i += (size_t)2048*256) {
            __nv_bfloat16 h, l; split2(img[i], h, l);
            g_iAh[i] = h; g_iAl[i] = l;
        }
        return;
    }
    b -= 2048;
    const float* W; int K, N; __nv_bfloat16 *Bh, *Bl; int bx, by;
    if (b < 64)             { W = Wc;             K = RELC; N = RELC; Bh = g_B1h; Bl = g_B1l; bx = b % 8;   by = b / 8; }
    else if (b < 576)       { b -= 64;  W = Wc + RELC*RELC; K = IMGF; N = RELC; Bh = g_B2h; Bl = g_B2l; bx = b % 8;   by = b / 8; }
    else if (b < 576+16384) { b -= 576; W = Ww;   K = F2;   N = F2;   Bh = g_Bwh; Bl = g_Bwl; bx = b % 128; by = b / 128; }
    else                    { b -= 16960; W = Wi; K = F2;   N = IMGF; Bh = g_Bih; Bl = g_Bil; bx = b % 64;  by = b / 64; }

    __shared__ float tile[32][33];
    int tx = threadIdx.x & 31, ty = threadIdx.x >> 5;
    int n0 = bx * 32, k0 = by * 32;
#pragma unroll
    for (int r = 0; r < 4; ++r)
        tile[ty + r*8][tx] = W[(size_t)(k0 + ty + r*8) * N + n0 + tx];
    __syncthreads();
#pragma unroll
    for (int r = 0; r < 4; ++r) {
        int n = n0 + ty + r*8, k = k0 + tx;
        float v = tile[tx][ty + r*8];
        __nv_bfloat16 h, l; split2(v, h, l);
        Bh[(size_t)n*K + k] = h;
        Bl[(size_t)n*K + k] = l;
    }
}

// ===========================================================================
// bf16-split GEMM tile body. CTA tile 128x128, BK=64, 16 warps 4x4 grid,
// 3-stage cp.async pipeline. nch = number of 64-wide K chunks to process;
// strideA/strideB = full row strides (split-K passes pointers offset to kbeg).
// EPI: 0 plain fp32, 1 +bias fp32, 2 sigmoid(acc+bias)*aux -> bf16 hi/lo
// ===========================================================================
#define STAGE_B 65536
#define NSTAGE 3
#define HG_SMEM (NSTAGE*STAGE_B)
#define GTHREADS 512

struct Frags {
    uint32_t ah[2][4];
    uint32_t al[2][4];
    uint32_t bh[2][4];
    uint32_t bl[2][4];
};

template<int EPI>
__device__ __forceinline__ void gemm_tile(
    int M, int N, int nch, int strideA, int strideB, int m0, int n0,
    const __nv_bfloat16* __restrict__ Ah, const __nv_bfloat16* __restrict__ Al,
    const __nv_bfloat16* __restrict__ Bh, const __nv_bfloat16* __restrict__ Bl,
    const float* __restrict__ bias, const float* __restrict__ aux,
    float* __restrict__ C,
    __nv_bfloat16* __restrict__ Ch, __nv_bfloat16* __restrict__ Cl,
    uint32_t sbase)
{
    const int tid = threadIdx.x;
    const int lid = tid & 31;
    const int wid = tid >> 5;       // 0..15
    const int wm = wid & 3;         // M strip (32 rows)
    const int wn = wid >> 2;        // N strip (32 cols)

    float acc[2][4][4];
#pragma unroll
    for (int i = 0; i < 2; ++i)
#pragma unroll
        for (int j = 0; j < 4; ++j)
#pragma unroll
            for (int e = 0; e < 4; ++e) acc[i][j][e] = 0.f;

    // loader mapping: 4 threads per 128B row, 2 x 16B segments each
    const int lrow = tid >> 2;           // 0..127
    const int lseg = (tid & 3) * 2;      // 0,2,4,6
    const int gmrow = m0 + lrow;
    const int a_ok = (gmrow < M) ? 16 : 0;
    const size_t aoff = (size_t)(a_ok ? gmrow : 0) * strideA;
    const size_t boff = (size_t)(n0 + lrow) * strideB;

    auto load_stage = [&](int c, int buf) {
        const int k0 = c << 6;
        const uint32_t sb = sbase + buf * STAGE_B;
        const char* pAh = (const char*)(Ah + aoff + k0);
        const char* pAl = (const char*)(Al + aoff + k0);
        const char* pBh = (const char*)(Bh + boff + k0);
        const char* pBl = (const char*)(Bl + boff + k0);
#pragma unroll
        for (int s = 0; s < 2; ++s) {
            const int colb = (lseg + s) * 16;
            const uint32_t sw = SWZ128((uint32_t)(lrow * 128 + colb));
            cp_async16(sb + sw,         pAh + colb, a_ok);
            cp_async16(sb + 16384 + sw, pAl + colb, a_ok);
            cp_async16(sb + 32768 + sw, pBh + colb, 16);
            cp_async16(sb + 49152 + sw, pBl + colb, 16);
        }
        CP_COMMIT();
    };

    // fragment lane components
    const int matA  = lid >> 3;
    const int rowA  = (lid & 7) + ((matA & 1) << 3);
    const int kselA = (matA >> 1) << 4;
    const int rowB  = (lid & 7) + ((matA >> 1) << 3);
    const int kselB = (matA & 1) << 4;

    auto load_frags = [&](uint32_t sb, int ks, Frags& F) {
        const int kb = ks << 5;
#pragma unroll
        for (int mi = 0; mi < 2; ++mi) {
            uint32_t off = SWZ128((uint32_t)((wm*32 + mi*16 + rowA) * 128 + kb + kselA));
            ldm4(F.ah[mi], sb + off);
            ldm4(F.al[mi], sb + 16384u + off);
        }
#pragma unroll
        for (int nb = 0; nb < 2; ++nb) {
            uint32_t off = SWZ128((uint32_t)((wn*32 + nb*16 + rowB) * 128 + kb + kselB));
            ldm4(F.bh[nb], sb + 32768u + off);
            ldm4(F.bl[nb], sb + 49152u + off);
        }
    };

    auto mma_all = [&](Frags& F) {
#pragma unroll
        for (int mi = 0; mi < 2; ++mi)
#pragma unroll
            for (int ni = 0; ni < 4; ++ni)
                mma16816(acc[mi][ni], F.ah[mi],
                         F.bh[ni >> 1][(ni & 1) * 2], F.bh[ni >> 1][(ni & 1) * 2 + 1]);
#pragma unroll
        for (int mi = 0; mi < 2; ++mi)
#pragma unroll
            for (int ni = 0; ni < 4; ++ni)
                mma16816(acc[mi][ni], F.ah[mi],
                         F.bl[ni >> 1][(ni & 1) * 2], F.bl[ni >> 1][(ni & 1) * 2 + 1]);
#pragma unroll
        for (int mi = 0; mi < 2; ++mi)
#pragma unroll
            for (int ni = 0; ni < 4; ++ni)
                mma16816(acc[mi][ni], F.al[mi],
                         F.bh[ni >> 1][(ni & 1) * 2], F.bh[ni >> 1][(ni & 1) * 2 + 1]);
    };

    load_stage(0, 0);
    if (nch > 1) load_stage(1, 1);
    for (int c = 0; c < nch; ++c) {
        if (c + 1 < nch) { CP_WAIT1(); } else { CP_WAIT0(); }
        __syncthreads();
        if (c + 2 < nch) load_stage(c + 2, (c + 2) % NSTAGE);
        const uint32_t sb = sbase + (c % NSTAGE) * STAGE_B;
#pragma unroll
        for (int ks = 0; ks < 4; ++ks) {
            Frags f;
            load_frags(sb, ks, f);
            mma_all(f);
        }
    }

    // epilogue
    const int er = lid >> 2;
    const int ec = (lid & 3) * 2;
#pragma unroll
    for (int mi = 0; mi < 2; ++mi) {
#pragma unroll
        for (int half = 0; half < 2; ++half) {
            const int gm = m0 + wm*32 + mi*16 + er + half*8;
            if (gm >= M) continue;
#pragma unroll
            for (int ni = 0; ni < 4; ++ni) {
                const int gn = n0 + wn*32 + ni*8 + ec;
                float v0 = acc[mi][ni][half*2 + 0];
                float v1 = acc[mi][ni][half*2 + 1];
                if (EPI == 0) {
                    float2 r; r.x = v0; r.y = v1;
                    *reinterpret_cast<float2*>(C + (size_t)gm*N + gn) = r;
                } else if (EPI == 1) {
                    float2 r; r.x = v0 + bias[gn]; r.y = v1 + bias[gn + 1];
                    *reinterpret_cast<float2*>(C + (size_t)gm*N + gn) = r;
                } else {
                    const size_t o = (size_t)gm*N + gn;
                    float g0 = sigmoidf_(v0 + bias[gn])     * aux[o];
                    float g1 = sigmoidf_(v1 + bias[gn + 1]) * aux[o + 1];
                    __nv_bfloat16 h0, l0, h1, l1;
                    split2(g0, h0, l0); split2(g1, h1, l1);
                    __nv_bfloat162 ph; ph.x = h0; ph.y = h1;
                    __nv_bfloat162 pl; pl.x = l0; pl.y = l1;
                    *reinterpret_cast<__nv_bfloat162*>(Ch + o) = ph;
                    *reinterpret_cast<__nv_bfloat162*>(Cl + o) = pl;
                }
            }
        }
    }
}

// gated GEMM (full-K, EPI2)
__global__ __launch_bounds__(GTHREADS, 1)
void hgemm_gated(const __nv_bfloat16* __restrict__ Ah, const __nv_bfloat16* __restrict__ Al,
                 const __nv_bfloat16* __restrict__ Bh, const __nv_bfloat16* __restrict__ Bl,
                 const float* __restrict__ bias, const float* __restrict__ aux,
                 __nv_bfloat16* __restrict__ Ch, __nv_bfloat16* __restrict__ Cl)
{
    extern __shared__ char sm[];
    gemm_tile<2>(ROWS, F2, F2/64, F2, F2, blockIdx.y * 128, blockIdx.x * 128,
                 Ah, Al, Bh, Bl, bias, aux, nullptr, Ch, Cl, smem_u32(sm));
}

// out GEMM split-K2: blockIdx.z = K half; writes fp32 partials (EPI0)
__global__ __launch_bounds__(GTHREADS, 1)
void hgemm_outk(const __nv_bfloat16* __restrict__ Ah, const __nv_bfloat16* __restrict__ Al,
                const __nv_bfloat16* __restrict__ Bh, const __nv_bfloat16* __restrict__ Bl,
                float* __restrict__ pout)
{
    extern __shared__ char sm[];
    const int part = blockIdx.z;
    const int kbeg = part * (F2/2);
    gemm_tile<0>(ROWS, IMGF, (F2/2)/64, F2, F2, blockIdx.y * 128, blockIdx.x * 128,
                 Ah + kbeg, Al + kbeg, Bh + kbeg, Bl + kbeg,
                 nullptr, nullptr, pout + (size_t)part*ROWS*IMGF, nullptr, nullptr,
                 smem_u32(sm));
}

// Merged dual: blocks [0,96) imgC split-K4 partials, [96,178) relC GEMM
__global__ __launch_bounds__(GTHREADS, 1)
void hgemm_dual(const __nv_bfloat16* __restrict__ iAh, const __nv_bfloat16* __restrict__ iAl,
                const __nv_bfloat16* __restrict__ B2h, const __nv_bfloat16* __restrict__ B2l,
                float* __restrict__ pimg,
                const __nv_bfloat16* __restrict__ rSh, const __nv_bfloat16* __restrict__ rSl,
                const __nv_bfloat16* __restrict__ B1h, const __nv_bfloat16* __restrict__ B1l,
                float* __restrict__ relC)
{
    extern __shared__ char sm[];
    const uint32_t sbase = smem_u32(sm);
    int blk = blockIdx.x;
    if (blk < 96) {
        int part = blk / 24;           // 0..3, K quarter
        int sub  = blk % 24;
        int kbeg = part * (IMGF/4);    // 512
        gemm_tile<0>(ROWS, RELC, (IMGF/4)/64, IMGF, IMGF,
                     (sub >> 1) * 128, (sub & 1) * 128,
                     iAh + kbeg, iAl + kbeg, B2h + kbeg, B2l + kbeg,
                     nullptr, nullptr, pimg + (size_t)part*ROWS*RELC, nullptr, nullptr, sbase);
    } else {
        int idx = blk - 96;
        gemm_tile<0>(RELROWS, RELC, RELC/64, RELC, RELC,
                     (idx >> 1) * 128, (idx & 1) * 128,
                     rSh, rSl, B1h, B1l, nullptr, nullptr, relC, nullptr, nullptr, sbase);
    }
}

// ===========================================================================
// Reductions for split-K
// ===========================================================================
__global__ void reduce_imgC(const float* __restrict__ bc)
{
    int row = blockIdx.x, c = threadIdx.x;
    size_t o = (size_t)row*RELC + c;
    const size_t st = (size_t)ROWS*RELC;
    g_imgC[o] = g_pimg[o] + g_pimg[o + st] + g_pimg[o + 2*st] + g_pimg[o + 3*st] + bc[c];
}

__global__ void reduce_out(const float* __restrict__ bi, float* __restrict__ out)
{
    const size_t n = (size_t)ROWS*IMGF;
    const size_t st = n;
    for (size_t i = (size_t)blockIdx.x*blockDim.x + threadIdx.x; i < n;
         i += (size_t)gridDim.x*blockDim.x) {
        out[i] = g_pout[i] + g_pout[i + st] + bi[i & (IMGF-1)];
    }
}

// ===========================================================================
// K4: D2[bn,j] = imgC[bn,j,:] . u[bn,:]
// ===========================================================================
__global__ void d2_kernel()
{
    int row = blockIdx.x, bn = row / PDIM, tid = threadIdx.x;
    float p = g_imgC[(size_t)row*RELC + tid] * g_u[bn*RELC + tid];
    __shared__ float sr[8];
#pragma unroll
    for (int off = 16; off; off >>= 1) p += __shfl_xor_sync(0xffffffffu, p, off);
    if ((tid & 31) == 0) sr[tid >> 5] = p;
    __syncthreads();
    if (tid == 0) {
        float s = 0.f;
#pragma unroll
        for (int k = 0; k < 8; ++k) s += sr[k];
        g_D2[row] = s;
    }
}

// ===========================================================================
// K5: per (bn,i): rw softmax -> gw softmax
// ===========================================================================
__global__ void gw_kernel()
{
    int blk = blockIdx.x;
    int bn = blk / PDIM, i = blk % PDIM;
    int b = bn / NR, m = bn % NR;
    int tid = threadIdx.x;
    int w = tid >> 5, lane = tid & 31;
    __shared__ float sL[PDIM], sD[PDIM], sred[2];
    const float* vv = g_v + bn*RELC;
    const float* uu = g_u + bn*RELC;

    for (int j = w; j < PDIM; j += 4) {
        int R  = m*(PDIM*PDIM) + i*PDIM + j;
        int si = R / (NR*PDIM);
        size_t rowbase = ((size_t)b*PDIM*PDIM + (size_t)si*PDIM + j) * RELC;
        const float* rs = g_relS + rowbase;
        const float* rc = g_relC + rowbase;
        float s1 = 0.f, s2 = 0.f;
        for (int c = lane; c < RELC; c += 32) { s1 += rs[c]*vv[c]; s2 += rc[c]*uu[c]; }
#pragma unroll
        for (int off = 16; off; off >>= 1) {
            s1 += __shfl_xor_sync(0xffffffffu, s1, off);
            s2 += __shfl_xor_sync(0xffffffffu, s2, off);
        }
        if (lane == 0) { sL[j] = s1; sD[j] = s2; }
    }
    __syncthreads();
    if (tid == 0) { float mx = -1e30f; for (int j=0;j<PDIM;++j) mx = fmaxf(mx, sL[j]); sred[0] = mx; }
    __syncthreads();
    if (tid < PDIM) sL[tid] = __expf(sL[tid] - sred[0]);
    __syncthreads();
    if (tid == 0) { float s = 0.f; for (int j=0;j<PDIM;++j) s += sL[j]; sred[1] = 1.0f/s; }
    __syncthreads();
    if (tid < PDIM) sL[tid] = sL[tid]*sred[1]*sD[tid] + g_D2[bn*PDIM + tid];
    __syncthreads();
    if (tid == 0) { float mx = -1e30f; for (int j=0;j<PDIM;++j) mx = fmaxf(mx, sL[j]); sred[0] = mx; }
    __syncthreads();
    if (tid < PDIM) sL[tid] = __expf(sL[tid] - sred[0]);
    __syncthreads();
    if (tid == 0) { float s = 0.f; for (int j=0;j<PDIM;++j) s += sL[j]; sred[1] = 1.0f/s; }
    __syncthreads();
    if (tid < PDIM) g_gw[(size_t)blk*PDIM + tid] = sL[tid]*sred[1];
}

// ===========================================================================
// K6: img_ws + assemble cii (fp32) + bf16 split of cii
// ===========================================================================
__global__ void imgws_kernel(const float* __restrict__ img)
{
    int chunk = blockIdx.x, bn = blockIdx.y, tid = threadIdx.x;
    __shared__ float sg[PDIM*PDIM];
    for (int t = tid; t < PDIM*PDIM; t += 256) sg[t] = g_gw[(size_t)bn*PDIM*PDIM + t];
    __syncthreads();

    int f = chunk*256 + tid;
    float acc[PDIM];
#pragma unroll
    for (int i = 0; i < PDIM; ++i) acc[i] = 0.f;
    const float* ib = img + (size_t)bn*PDIM*IMGF + f;
#pragma unroll 4
    for (int j = 0; j < PDIM; ++j) {
        float vj = ib[(size_t)j*IMGF];
#pragma unroll
        for (int i = 0; i < PDIM; ++i) acc[i] += sg[i*PDIM + j] * vj;
    }
    size_t cb = (size_t)bn*PDIM*F2 + f;
#pragma unroll
    for (int i = 0; i < PDIM; ++i) {
        float iv = ib[(size_t)i*IMGF];
        size_t o0 = cb + (size_t)i*F2;
        size_t o1 = o0 + IMGF;
        g_cii[o0] = iv;
        g_cii[o1] = acc[i];
        __nv_bfloat16 h, l;
        split2(iv, h, l);     g_cAh[o0] = h; g_cAl[o0] = l;
        split2(acc[i], h, l); g_cAh[o1] = h; g_cAl[o1] = l;
    }
}

// ===========================================================================
// Launch
// ===========================================================================
extern "C" void kernel_launch(void* const* d_in, const int* in_sizes, int n_in,
                              void* d_out, int out_size)
{
    const float* relation = (const float*)d_in[0];
    const float* img      = (const float*)d_in[1];
    const float* ques     = (const float*)d_in[2];
    const float* Wcr      = (const float*)d_in[3];
    const float* bcr      = (const float*)d_in[4];
    const float* Wq       = (const float*)d_in[5];
    const float* bq       = (const float*)d_in[6];
    const float* Wrw      = (const float*)d_in[7];
    const float* Wc       = (const float*)d_in[9];
    const float* bc       = (const float*)d_in[10];
    const float* Wg       = (const float*)d_in[11];
    const float* Ww       = (const float*)d_in[13];
    const float* bw       = (const float*)d_in[14];
    const float* Wi       = (const float*)d_in[15];
    const float* bi       = (const float*)d_in[16];
    float* out = (float*)d_out;

    cudaFuncSetAttribute(hgemm_gated, cudaFuncAttributeMaxDynamicSharedMemorySize, HG_SMEM);
    cudaFuncSetAttribute(hgemm_outk,  cudaFuncAttributeMaxDynamicSharedMemorySize, HG_SMEM);
    cudaFuncSetAttribute(hgemm_dual,  cudaFuncAttributeMaxDynamicSharedMemorySize, HG_SMEM);

    float *p_relC, *p_pimg, *p_pout, *p_cii;
    __nv_bfloat16 *p_rSh,*p_rSl,*p_iAh,*p_iAl,*p_cAh,*p_cAl,*p_gAh,*p_gAl;
    __nv_bfloat16 *p_B1h,*p_B1l,*p_B2h,*p_B2l,*p_Bwh,*p_Bwl,*p_Bih,*p_Bil;
    cudaGetSymbolAddress((void**)&p_relC, g_relC);
    cudaGetSymbolAddress((void**)&p_pimg, g_pimg);
    cudaGetSymbolAddress((void**)&p_pout, g_pout);
    cudaGetSymbolAddress((void**)&p_cii,  g_cii);
    cudaGetSymbolAddress((void**)&p_rSh, g_rSh); cudaGetSymbolAddress((void**)&p_rSl, g_rSl);
    cudaGetSymbolAddress((void**)&p_iAh, g_iAh); cudaGetSymbolAddress((void**)&p_iAl, g_iAl);
    cudaGetSymbolAddress((void**)&p_cAh, g_cAh); cudaGetSymbolAddress((void**)&p_cAl, g_cAl);
    cudaGetSymbolAddress((void**)&p_gAh, g_gAh); cudaGetSymbolAddress((void**)&p_gAl, g_gAl);
    cudaGetSymbolAddress((void**)&p_B1h, g_B1h); cudaGetSymbolAddress((void**)&p_B1l, g_B1l);
    cudaGetSymbolAddress((void**)&p_B2h, g_B2h); cudaGetSymbolAddress((void**)&p_B2l, g_B2l);
    cudaGetSymbolAddress((void**)&p_Bwh, g_Bwh); cudaGetSymbolAddress((void**)&p_Bwl, g_Bwl);
    cudaGetSymbolAddress((void**)&p_Bih, g_Bih); cudaGetSymbolAddress((void**)&p_Bil, g_Bil);

    // 1. relS (fp32 + split)
    rels_kernel<<<RELROWS, RELC>>>(relation, Wcr, bcr);
    // 2. question vectors
    ques_kernel<<<BN, RELC>>>(ques, Wq, bq, Wrw, Wg);
    // 3. all operand conversions (merged)
    convert_all<<<2048 + 64 + 512 + 16384 + 8192, 256>>>(img, Wc, Ww, Wi);
    // 4. imgC split-K4 + relC GEMM merged (178 CTAs)  <-- profiled slot
    hgemm_dual<<<178, GTHREADS, HG_SMEM>>>(p_iAh, p_iAl, p_B2h, p_B2l, p_pimg,
                                           p_rSh, p_rSl, p_B1h, p_B1l, p_relC);
    // 5. imgC reduce (+bc)
    reduce_imgC<<<ROWS, RELC>>>(bc);
    // 6. D2
    d2_kernel<<<ROWS, RELC>>>();
    // 7. attention weights
    gw_kernel<<<ROWS, 128>>>();
    // 8. img_ws + cii (+ split)
    imgws_kernel<<<dim3(IMGF/256, BN), 256>>>(img);
    // 9. gated = sigmoid(cii@Ww + bw)*cii -> bf16 split  (384 CTAs, 64 chunks)
    hgemm_gated<<<dim3(F2/128, (ROWS+127)/128), GTHREADS, HG_SMEM>>>(
        p_cAh, p_cAl, p_Bwh, p_Bwl, bw, p_cii, p_gAh, p_gAl);
    // 10. out partials: split-K2 (384 CTAs, 32 chunks each)
    hgemm_outk<<<dim3(IMGF/128, (ROWS+127)/128, 2), GTHREADS, HG_SMEM>>>(
        p_gAh, p_gAl, p_Bih, p_Bil, p_pout);
    // 11. out = p0 + p1 + bi
    reduce_out<<<4096, 256>>>(bi, out);
}